// round 10
// baseline (speedup 1.0000x reference)
#include <cuda_runtime.h>
#include <cuda_bf16.h>
#include <cuda_fp16.h>
#include <math.h>
#include <stdint.h>

#define NB 8
#define HH 128
#define WW 128
#define NC 192
#define C3 576
#define HEADS 4
#define CH 48
#define HW 16384
#define BNT 32
#define KDIM 192

// ---------------- scratch ----------------
__device__ float g_qkv[(size_t)NB * HW * C3];
__device__ __nv_bfloat16 g_qh[(size_t)NB * HW * NC];
__device__ __nv_bfloat16 g_ql[(size_t)NB * HW * NC];
__device__ __nv_bfloat16 g_kh[(size_t)NB * HW * NC];
__device__ __nv_bfloat16 g_kl[(size_t)NB * HW * NC];
__device__ float g_v[(size_t)NB * HW * NC];
__device__ float g_o[(size_t)NB * HW * NC];
__device__ float g_attn[BNT * CH * CH];
__device__ float g_ssq_q[BNT * CH];
__device__ float g_ssq_k[BNT * CH];
// GEMM weights: fp16 hi/lo, [N][K]
__device__ __half g_wqkv_h[C3 * KDIM];
__device__ __half g_wqkv_l[C3 * KDIM];
__device__ __half g_wproj_h[NC * KDIM];
__device__ __half g_wproj_l[NC * KDIM];

// ---------------- helpers ----------------
__device__ __forceinline__ uint32_t smem_u32(const void* p) {
    uint32_t a;
    asm("{ .reg .u64 t; cvta.to.shared.u64 t, %1; cvt.u32.u64 %0, t; }" : "=r"(a) : "l"(p));
    return a;
}
__device__ __forceinline__ uint32_t pk_hi(float a, float b) {   // bf16 pack (dwconv/qk path)
    __nv_bfloat16 ha = __float2bfloat16(a), hb = __float2bfloat16(b);
    uint16_t ra = *(uint16_t*)&ha, rb = *(uint16_t*)&hb;
    return (uint32_t)ra | ((uint32_t)rb << 16);
}
__device__ __forceinline__ uint32_t pk_lo(float a, float b) {
    __nv_bfloat16 ha = __float2bfloat16(a), hb = __float2bfloat16(b);
    float la = a - __bfloat162float(ha), lb = b - __bfloat162float(hb);
    __nv_bfloat16 xa = __float2bfloat16(la), xb = __float2bfloat16(lb);
    uint16_t ra = *(uint16_t*)&xa, rb = *(uint16_t*)&xb;
    return (uint32_t)ra | ((uint32_t)rb << 16);
}
__device__ __forceinline__ uint32_t pkh(float a, float b) {     // fp16x2 pack (GEMM path)
    __half2 h = __floats2half2_rn(a, b);
    return *(uint32_t*)&h;
}
__device__ __forceinline__ float bf_lo(uint32_t v) { return __uint_as_float(v << 16); }
__device__ __forceinline__ float bf_hi(uint32_t v) { return __uint_as_float(v & 0xffff0000u); }

__device__ __forceinline__ void mma16816(float* c, const uint32_t* a, const uint32_t* b) {
    asm volatile(
        "mma.sync.aligned.m16n8k16.row.col.f32.bf16.bf16.f32 "
        "{%0,%1,%2,%3}, {%4,%5,%6,%7}, {%8,%9}, {%0,%1,%2,%3};\n"
        : "+f"(c[0]), "+f"(c[1]), "+f"(c[2]), "+f"(c[3])
        : "r"(a[0]), "r"(a[1]), "r"(a[2]), "r"(a[3]), "r"(b[0]), "r"(b[1]));
}
__device__ __forceinline__ void mma16816h(float* c, const uint32_t* a, const uint32_t* b) {
    asm volatile(
        "mma.sync.aligned.m16n8k16.row.col.f32.f16.f16.f32 "
        "{%0,%1,%2,%3}, {%4,%5,%6,%7}, {%8,%9}, {%0,%1,%2,%3};\n"
        : "+f"(c[0]), "+f"(c[1]), "+f"(c[2]), "+f"(c[3])
        : "r"(a[0]), "r"(a[1]), "r"(a[2]), "r"(a[3]), "r"(b[0]), "r"(b[1]));
}
__device__ __forceinline__ void ldmx4(uint32_t* r, uint32_t addr) {
    asm volatile("ldmatrix.sync.aligned.m8n8.x4.shared.b16 {%0,%1,%2,%3}, [%4];"
        : "=r"(r[0]), "=r"(r[1]), "=r"(r[2]), "=r"(r[3]) : "r"(addr));
}
#define CP_ASYNC16(dst, src) asm volatile("cp.async.ca.shared.global [%0], [%1], 16;" :: "r"(dst), "l"(src))
#define CP_COMMIT()          asm volatile("cp.async.commit_group;" ::: "memory")
#define CP_WAIT(n)           asm volatile("cp.async.wait_group %0;" :: "n"(n) : "memory")

// ---------------- weight prep (3 launches so slot 4 = qkv GEMM in ncu) ----------------
__global__ void wprep_qkvw_kernel(const float* __restrict__ qkvw)
{
    int i = blockIdx.x * 256 + threadIdx.x;
    if (i < C3 * KDIM) {
        int n = i / KDIM, k = i % KDIM;
        float v = qkvw[(size_t)k * C3 + n];
        __half h = __float2half_rn(v);
        g_wqkv_h[i] = h;
        g_wqkv_l[i] = __float2half_rn(v - __half2float(h));
    }
}
__global__ void wprep_projw_kernel(const float* __restrict__ projw)
{
    int i = blockIdx.x * 256 + threadIdx.x;
    if (i < NC * KDIM) {
        int n = i / KDIM, k = i % KDIM;
        float v = projw[(size_t)k * NC + n];
        __half h = __float2half_rn(v);
        g_wproj_h[i] = h;
        g_wproj_l[i] = __float2half_rn(v - __half2float(h));
    }
}
__global__ void zero_kernel()
{
    int i = blockIdx.x * 256 + threadIdx.x;
    if (i < BNT * CH * CH) g_attn[i] = 0.f;
    if (i < BNT * CH) { g_ssq_q[i] = 0.f; g_ssq_k[i] = 0.f; }
}

// ---------------- fp16 2-term GEMM: [M,192]fp32 x W[N,192]fp16(hi/lo) -> [M,N]fp32 ----------------
// D = A16*Bh + A16*Bl (A rounded to fp16; B hi+lo exact). CTA tile 128x64, 256 thr,
// 8 warps (4M x 2N), warp tile 32x32. smem 102400 -> 2 CTAs/SM.
#define ASTRIDE 200
#define ROWB    (ASTRIDE * 2)          // 400 bytes per row
#define OFF_A   0                       // 128 * 400 = 51200
#define OFF_BH  (128 * ROWB)            // 51200
#define OFF_BL  (128 * ROWB + 64 * ROWB)// 76800
#define GEMM_SMEM (128 * ROWB + 2 * 64 * ROWB)   // 102400

__global__ __launch_bounds__(256, 2) void gemm_fp16_split(
    const float* __restrict__ A, const __half* __restrict__ Wh,
    const __half* __restrict__ Wl, float* __restrict__ Cout, int Ntot)
{
    extern __shared__ char smem[];
    const uint32_t sbase = smem_u32(smem);
    const uint32_t sA  = sbase + OFF_A;
    const uint32_t sBh = sbase + OFF_BH;
    const uint32_t sBl = sbase + OFF_BL;

    const int t = threadIdx.x;
    const int warp = t >> 5, lane = t & 31;
    const int grp = lane >> 2, tig = lane & 3;
    const int warpM = warp >> 1, warpN = warp & 1;      // 4 x 2
    const size_t m0 = (size_t)blockIdx.x * 128;
    const int nChunks = Ntot >> 6;

    const uint32_t aOff = (uint32_t)(warpM * 32 + (lane & 15)) * ROWB + ((lane >> 4) * 16);
    const uint32_t bOff = (uint32_t)(warpN * 32 + ((lane >> 4) * 8) + (lane & 7)) * ROWB
                          + (((lane >> 3) & 1) * 16);

    // ---- issue B chunk 0 load ----
    {
        const uint4* bh = (const uint4*)Wh;
        const uint4* bl = (const uint4*)Wl;
#pragma unroll
        for (int i = t; i < 1536; i += 256) {          // 64 rows * 24 uint4
            int row = i / 24, cb = (i % 24) * 16;
            uint32_t o = (uint32_t)row * ROWB + cb;
            CP_ASYNC16(sBh + o, bh + i);
            CP_ASYNC16(sBl + o, bl + i);
        }
        CP_COMMIT();
    }
    // ---- A: 128 rows fp32 -> single fp16 plane (overlaps B0 load) ----
    {
        int row = t >> 1, half = t & 1;
        const float4* ar = (const float4*)(A + (m0 + row) * KDIM + half * 96);
        __half* ap = (__half*)(smem + OFF_A) + row * ASTRIDE + half * 96;
#pragma unroll
        for (int j = 0; j < 24; j++) {
            float4 v = ar[j];
            *(uint32_t*)(ap + j * 4)     = pkh(v.x, v.y);
            *(uint32_t*)(ap + j * 4 + 2) = pkh(v.z, v.w);
        }
    }
    CP_WAIT(0);
    __syncthreads();

    float c[2][4][4];

    for (int nc = 0; nc < nChunks; nc++) {
#pragma unroll
        for (int mi = 0; mi < 2; mi++)
#pragma unroll
            for (int nj = 0; nj < 4; nj++)
#pragma unroll
                for (int j = 0; j < 4; j++) c[mi][nj][j] = 0.f;

#pragma unroll
        for (int ks = 0; ks < 12; ks++) {
            const uint32_t k32 = ks * 32;
            uint32_t a0[4], a1[4], bh0[4], bh1[4], bl0[4], bl1[4];
            ldmx4(a0, sA + aOff + k32);
            ldmx4(a1, sA + aOff + 16 * ROWB + k32);
            ldmx4(bh0, sBh + bOff + k32);
            ldmx4(bh1, sBh + bOff + 16 * ROWB + k32);
            ldmx4(bl0, sBl + bOff + k32);
            ldmx4(bl1, sBl + bOff + 16 * ROWB + k32);
            // sweep 1: A * Bh (accumulator reuse distance 8)
            mma16816h(c[0][0], a0, &bh0[0]);
            mma16816h(c[0][1], a0, &bh0[2]);
            mma16816h(c[0][2], a0, &bh1[0]);
            mma16816h(c[0][3], a0, &bh1[2]);
            mma16816h(c[1][0], a1, &bh0[0]);
            mma16816h(c[1][1], a1, &bh0[2]);
            mma16816h(c[1][2], a1, &bh1[0]);
            mma16816h(c[1][3], a1, &bh1[2]);
            // sweep 2: A * Bl
            mma16816h(c[0][0], a0, &bl0[0]);
            mma16816h(c[0][1], a0, &bl0[2]);
            mma16816h(c[0][2], a0, &bl1[0]);
            mma16816h(c[0][3], a0, &bl1[2]);
            mma16816h(c[1][0], a1, &bl0[0]);
            mma16816h(c[1][1], a1, &bl0[2]);
            mma16816h(c[1][2], a1, &bl1[0]);
            mma16816h(c[1][3], a1, &bl1[2]);
        }
        __syncthreads();   // all warps done reading this B chunk

        // issue next B chunk load (overlaps epilogue stores; partner CTA hides rest)
        if (nc + 1 < nChunks) {
            const uint4* bh = (const uint4*)(Wh + (size_t)(nc + 1) * 64 * KDIM);
            const uint4* bl = (const uint4*)(Wl + (size_t)(nc + 1) * 64 * KDIM);
#pragma unroll
            for (int i = t; i < 1536; i += 256) {
                int row = i / 24, cb = (i % 24) * 16;
                uint32_t o = (uint32_t)row * ROWB + cb;
                CP_ASYNC16(sBh + o, bh + i);
                CP_ASYNC16(sBl + o, bl + i);
            }
            CP_COMMIT();
        }

        // epilogue: store 128x64 chunk
        const int n0 = nc * 64;
#pragma unroll
        for (int mi = 0; mi < 2; mi++) {
            size_t row = m0 + warpM * 32 + mi * 16 + grp;
#pragma unroll
            for (int nj = 0; nj < 4; nj++) {
                int col = n0 + warpN * 32 + nj * 8 + tig * 2;
                *(float2*)(Cout + row * Ntot + col) = make_float2(c[mi][nj][0], c[mi][nj][1]);
                *(float2*)(Cout + (row + 8) * Ntot + col) = make_float2(c[mi][nj][2], c[mi][nj][3]);
            }
        }
        CP_WAIT(0);
        __syncthreads();
    }
}

// ---------------- depthwise 3x3 SAME + split (naive/coalesced; q/k -> bf16 hi/lo) ----------------
__global__ __launch_bounds__(256) void dwconv_split_kernel(const float* __restrict__ w)
{
    int gid = blockIdx.x * 256 + threadIdx.x;
    int c4 = gid % 144;
    int p = gid / 144;
    int x = p % WW;
    int y = (p / WW) % HH;
    int b = p / HW;
    int c = c4 * 4;

    float4 acc = make_float4(0.f, 0.f, 0.f, 0.f);
#pragma unroll
    for (int dy = -1; dy <= 1; dy++) {
        int yy = y + dy;
        if (yy < 0 || yy >= HH) continue;
#pragma unroll
        for (int dx = -1; dx <= 1; dx++) {
            int xx = x + dx;
            if (xx < 0 || xx >= WW) continue;
            const float4 iv = *(const float4*)(g_qkv + ((size_t)((b * HH + yy) * WW + xx)) * C3 + c);
            const float4 wv = *(const float4*)(w + (size_t)((dy + 1) * 3 + (dx + 1)) * C3 + c);
            acc.x = fmaf(iv.x, wv.x, acc.x);
            acc.y = fmaf(iv.y, wv.y, acc.y);
            acc.z = fmaf(iv.z, wv.z, acc.z);
            acc.w = fmaf(iv.w, wv.w, acc.w);
        }
    }
    if (c < NC) {
        int cc = c;
        *(uint2*)&g_qh[(size_t)p * NC + cc] = make_uint2(pk_hi(acc.x, acc.y), pk_hi(acc.z, acc.w));
        *(uint2*)&g_ql[(size_t)p * NC + cc] = make_uint2(pk_lo(acc.x, acc.y), pk_lo(acc.z, acc.w));
    } else if (c < 2 * NC) {
        int cc = c - NC;
        *(uint2*)&g_kh[(size_t)p * NC + cc] = make_uint2(pk_hi(acc.x, acc.y), pk_hi(acc.z, acc.w));
        *(uint2*)&g_kl[(size_t)p * NC + cc] = make_uint2(pk_lo(acc.x, acc.y), pk_lo(acc.z, acc.w));
    } else {
        int cc = c - 2 * NC;
        *(float4*)&g_v[(size_t)p * NC + cc] = acc;
    }
}

// ---------------- QK^T via mma.sync bf16-split + fused ssq ----------------
#define QK_PLANE 25344                     // 48 rows * 528 bytes
#define QK_SMEM  (4 * QK_PLANE)            // 101376

__global__ __launch_bounds__(256) void qk_mma_kernel()
{
    extern __shared__ char qsm[];
    const uint32_t sb = smem_u32(qsm);
    const int t = threadIdx.x, lane = t & 31, warp = t >> 5;
    const int grp = lane >> 2, tig = lane & 3;
    const int bn = blockIdx.x;
    const int sbase0 = blockIdx.y * 2048;

    const uint32_t aAddr = sb + (uint32_t)(lane & 15) * 528 + warp * 64 + ((lane >> 4) * 16);
    const uint32_t bAddr = sb + (uint32_t)(((lane >> 4) * 8) + (lane & 7)) * 528 + warp * 64
                           + (((lane >> 3) & 1) * 16);

    float c[3][6][4];
#pragma unroll
    for (int mi = 0; mi < 3; mi++)
#pragma unroll
        for (int nj = 0; nj < 6; nj++)
#pragma unroll
            for (int j = 0; j < 4; j++) c[mi][nj][j] = 0.f;
    float sq[3][2] = {{0.f,0.f},{0.f,0.f},{0.f,0.f}};
    float sk[3][2] = {{0.f,0.f},{0.f,0.f},{0.f,0.f}};

    for (int stage = 0; stage < 8; stage++) {
        const int sbase = sbase0 + stage * 256;
        const __nv_bfloat16* gp0 = g_qh; const __nv_bfloat16* gp1 = g_ql;
        const __nv_bfloat16* gp2 = g_kh; const __nv_bfloat16* gp3 = g_kl;
#pragma unroll
        for (int pl = 0; pl < 4; pl++) {
            const __nv_bfloat16* gp = (pl == 0) ? gp0 : (pl == 1) ? gp1 : (pl == 2) ? gp2 : gp3;
            uint32_t sp = sb + pl * QK_PLANE;
            for (int i = t; i < 1536; i += 256) {
                int r = i >> 5, seg = i & 31;
                const void* src = gp + (((size_t)(bn * 48 + r)) << 14) + sbase + seg * 8;
                CP_ASYNC16(sp + (uint32_t)r * 528 + seg * 16, src);
            }
        }
        CP_COMMIT();
        CP_WAIT(0);
        __syncthreads();

#pragma unroll
        for (int ks = 0; ks < 2; ks++) {
            const uint32_t kb = ks * 32;
            uint32_t ah[3][4], al[3][4], bh[3][4], bl[3][4];
#pragma unroll
            for (int mi = 0; mi < 3; mi++) {
                ldmx4(ah[mi], aAddr + (uint32_t)(mi * 16) * 528 + kb);
                ldmx4(al[mi], aAddr + QK_PLANE + (uint32_t)(mi * 16) * 528 + kb);
            }
#pragma unroll
            for (int pj = 0; pj < 3; pj++) {
                ldmx4(bh[pj], bAddr + 2 * QK_PLANE + (uint32_t)(pj * 16) * 528 + kb);
                ldmx4(bl[pj], bAddr + 3 * QK_PLANE + (uint32_t)(pj * 16) * 528 + kb);
            }
#pragma unroll
            for (int mi = 0; mi < 3; mi++)
#pragma unroll
                for (int r = 0; r < 4; r++) {
                    float f0 = bf_lo(ah[mi][r]) + bf_lo(al[mi][r]);
                    float f1 = bf_hi(ah[mi][r]) + bf_hi(al[mi][r]);
                    sq[mi][r & 1] = fmaf(f0, f0, fmaf(f1, f1, sq[mi][r & 1]));
                }
#pragma unroll
            for (int pj = 0; pj < 3; pj++)
#pragma unroll
                for (int r = 0; r < 4; r++) {
                    float f0 = bf_lo(bh[pj][r]) + bf_lo(bl[pj][r]);
                    float f1 = bf_hi(bh[pj][r]) + bf_hi(bl[pj][r]);
                    sk[pj][r >> 1] = fmaf(f0, f0, fmaf(f1, f1, sk[pj][r >> 1]));
                }
#pragma unroll
            for (int mi = 0; mi < 3; mi++)
#pragma unroll
                for (int pj = 0; pj < 3; pj++) {
                    mma16816(c[mi][2 * pj],     ah[mi], &bh[pj][0]);
                    mma16816(c[mi][2 * pj + 1], ah[mi], &bh[pj][2]);
                }
#pragma unroll
            for (int mi = 0; mi < 3; mi++)
#pragma unroll
                for (int pj = 0; pj < 3; pj++) {
                    mma16816(c[mi][2 * pj],     ah[mi], &bl[pj][0]);
                    mma16816(c[mi][2 * pj + 1], ah[mi], &bl[pj][2]);
                }
#pragma unroll
            for (int mi = 0; mi < 3; mi++)
#pragma unroll
                for (int pj = 0; pj < 3; pj++) {
                    mma16816(c[mi][2 * pj],     al[mi], &bh[pj][0]);
                    mma16816(c[mi][2 * pj + 1], al[mi], &bh[pj][2]);
                }
        }
        __syncthreads();
    }

    float* attn_s = (float*)qsm;
    float* ssq_qs = attn_s + 2304;
    float* ssq_ks = ssq_qs + 48;
    for (int i = t; i < 2400; i += 256) attn_s[i] = 0.f;
    __syncthreads();

#pragma unroll
    for (int mi = 0; mi < 3; mi++)
#pragma unroll
        for (int nj = 0; nj < 6; nj++) {
            int row = mi * 16 + grp, col = nj * 8 + tig * 2;
            atomicAdd(&attn_s[row * 48 + col],           c[mi][nj][0]);
            atomicAdd(&attn_s[row * 48 + col + 1],       c[mi][nj][1]);
            atomicAdd(&attn_s[(row + 8) * 48 + col],     c[mi][nj][2]);
            atomicAdd(&attn_s[(row + 8) * 48 + col + 1], c[mi][nj][3]);
        }
#pragma unroll
    for (int mi = 0; mi < 3; mi++)
#pragma unroll
        for (int h = 0; h < 2; h++) {
            float v = sq[mi][h];
            v += __shfl_xor_sync(~0u, v, 1);
            v += __shfl_xor_sync(~0u, v, 2);
            if (tig == 0) atomicAdd(&ssq_qs[mi * 16 + h * 8 + grp], v);
            float u = sk[mi][h];
            u += __shfl_xor_sync(~0u, u, 1);
            u += __shfl_xor_sync(~0u, u, 2);
            if (tig == 0) atomicAdd(&ssq_ks[mi * 16 + h * 8 + grp], u);
        }
    __syncthreads();

    for (int i = t; i < 2304; i += 256) atomicAdd(&g_attn[bn * 2304 + i], attn_s[i]);
    if (t < 48) atomicAdd(&g_ssq_q[bn * 48 + t], ssq_qs[t]);
    else if (t < 96) atomicAdd(&g_ssq_k[bn * 48 + t - 48], ssq_ks[t - 48]);
}

// ---------------- softmax with l2-norm scaling + temperature ----------------
__global__ void softmax48_kernel(const float* __restrict__ temp)
{
    int row = blockIdx.x;
    int bn = row / CH;
    int n = bn & (HEADS - 1);
    int l = threadIdx.x;
    float tf = temp[n];
    float iq = rsqrtf(fmaxf(g_ssq_q[row], 1e-12f));
    float* arow = g_attn + (size_t)row * CH;

    float ik0 = rsqrtf(fmaxf(g_ssq_k[bn * CH + l], 1e-12f));
    float v0 = arow[l] * iq * ik0 * tf;
    float v1 = -3.0e38f;
    if (l < 16) {
        float ik1 = rsqrtf(fmaxf(g_ssq_k[bn * CH + l + 32], 1e-12f));
        v1 = arow[l + 32] * iq * ik1 * tf;
    }
    float m = fmaxf(v0, v1);
#pragma unroll
    for (int o = 16; o > 0; o >>= 1) m = fmaxf(m, __shfl_xor_sync(~0u, m, o));
    float e0 = expf(v0 - m);
    float e1 = (l < 16) ? expf(v1 - m) : 0.f;
    float s = e0 + e1;
#pragma unroll
    for (int o = 16; o > 0; o >>= 1) s += __shfl_xor_sync(~0u, s, o);
    float inv = 1.f / s;
    arow[l] = e0 * inv;
    if (l < 16) arow[l + 32] = e1 * inv;
}

// ---------------- out = attn @ V ----------------
__global__ __launch_bounds__(256) void av_kernel()
{
    int bn = blockIdx.x;
    int s2 = blockIdx.y * 256 + threadIdx.x;

    __shared__ float As[CH * CH];
    for (int f = threadIdx.x; f < CH * CH; f += 256) As[f] = g_attn[bn * CH * CH + f];
    __syncthreads();

    const float2* vb = (const float2*)(g_v + (size_t)bn * CH * HW) + s2;
    float2 vr[CH];
#pragma unroll
    for (int e = 0; e < CH; e++) vr[e] = vb[(size_t)e * (HW / 2)];

    float2* ob = (float2*)(g_o + (size_t)bn * CH * HW) + s2;
    for (int d = 0; d < CH; d++) {
        float2 a = make_float2(0.f, 0.f);
#pragma unroll
        for (int e = 0; e < CH; e++) {
            float w = As[d * CH + e];
            a.x = fmaf(w, vr[e].x, a.x);
            a.y = fmaf(w, vr[e].y, a.y);
        }
        ob[(size_t)d * (HW / 2)] = a;
    }
}

// ---------------- launch ----------------
extern "C" void kernel_launch(void* const* d_in, const int* in_sizes, int n_in,
                              void* d_out, int out_size)
{
    const float* x      = (const float*)d_in[0];
    const float* qkv_w  = (const float*)d_in[1];
    const float* dw_w   = (const float*)d_in[2];
    const float* proj_w = (const float*)d_in[3];
    const float* temp   = (const float*)d_in[4];
    float* out = (float*)d_out;

    float *qkv_buf, *o_buf;
    cudaGetSymbolAddress((void**)&qkv_buf, g_qkv);
    cudaGetSymbolAddress((void**)&o_buf, g_o);
    __half *wqh, *wql, *wph, *wpl;
    cudaGetSymbolAddress((void**)&wqh, g_wqkv_h);
    cudaGetSymbolAddress((void**)&wql, g_wqkv_l);
    cudaGetSymbolAddress((void**)&wph, g_wproj_h);
    cudaGetSymbolAddress((void**)&wpl, g_wproj_l);

    cudaFuncSetAttribute(gemm_fp16_split, cudaFuncAttributeMaxDynamicSharedMemorySize, GEMM_SMEM);
    cudaFuncSetAttribute(qk_mma_kernel, cudaFuncAttributeMaxDynamicSharedMemorySize, QK_SMEM);

    const int M = NB * HW;

    // launches 1-3: prep (slot 4 = qkv GEMM gets profiled)
    wprep_qkvw_kernel<<<(C3 * KDIM + 255) / 256, 256>>>(qkv_w);
    wprep_projw_kernel<<<(NC * KDIM + 255) / 256, 256>>>(proj_w);
    zero_kernel<<<(BNT * CH * CH + 255) / 256, 256>>>();

    // 4) qkv = x @ qkv_w   <-- profiled slot
    gemm_fp16_split<<<M / 128, 256, GEMM_SMEM>>>(x, wqh, wql, qkv_buf, C3);

    // 5) depthwise 3x3 + split
    dwconv_split_kernel<<<(NB * HW * (C3 / 4)) / 256, 256>>>(dw_w);

    // 6) QK^T (tensor cores) + fused square sums
    qk_mma_kernel<<<dim3(BNT, 8), 256, QK_SMEM>>>();

    // 7) scale + softmax
    softmax48_kernel<<<BNT * CH, 32>>>(temp);

    // 8) out = attn @ V
    av_kernel<<<dim3(BNT, HW / 512), 256>>>();

    // 9) projection
    gemm_fp16_split<<<M / 128, 256, GEMM_SMEM>>>(o_buf, wph, wpl, out, NC);
}

// round 11
// speedup vs baseline: 1.0021x; 1.0021x over previous
#include <cuda_runtime.h>
#include <cuda_bf16.h>
#include <cuda_fp16.h>
#include <math.h>
#include <stdint.h>

#define NB 8
#define HH 128
#define WW 128
#define NC 192
#define C3 576
#define HEADS 4
#define CH 48
#define HW 16384
#define BNT 32
#define KDIM 192

// ---------------- scratch ----------------
__device__ float g_qkv[(size_t)NB * HW * C3];
__device__ __nv_bfloat16 g_qh[(size_t)NB * HW * NC];
__device__ __nv_bfloat16 g_ql[(size_t)NB * HW * NC];
__device__ __nv_bfloat16 g_kh[(size_t)NB * HW * NC];
__device__ __nv_bfloat16 g_kl[(size_t)NB * HW * NC];
__device__ float g_v[(size_t)NB * HW * NC];
__device__ float g_o[(size_t)NB * HW * NC];
__device__ float g_attn[BNT * CH * CH];
__device__ float g_ssq_q[BNT * CH];
__device__ float g_ssq_k[BNT * CH];
// GEMM weights: fp16 hi/lo, [N][K]
__device__ __half g_wqkv_h[C3 * KDIM];
__device__ __half g_wqkv_l[C3 * KDIM];
__device__ __half g_wproj_h[NC * KDIM];
__device__ __half g_wproj_l[NC * KDIM];

// ---------------- helpers ----------------
__device__ __forceinline__ uint32_t smem_u32(const void* p) {
    uint32_t a;
    asm("{ .reg .u64 t; cvta.to.shared.u64 t, %1; cvt.u32.u64 %0, t; }" : "=r"(a) : "l"(p));
    return a;
}
__device__ __forceinline__ uint32_t pk_hi(float a, float b) {   // bf16 pack (dwconv/qk path)
    __nv_bfloat16 ha = __float2bfloat16(a), hb = __float2bfloat16(b);
    uint16_t ra = *(uint16_t*)&ha, rb = *(uint16_t*)&hb;
    return (uint32_t)ra | ((uint32_t)rb << 16);
}
__device__ __forceinline__ uint32_t pk_lo(float a, float b) {
    __nv_bfloat16 ha = __float2bfloat16(a), hb = __float2bfloat16(b);
    float la = a - __bfloat162float(ha), lb = b - __bfloat162float(hb);
    __nv_bfloat16 xa = __float2bfloat16(la), xb = __float2bfloat16(lb);
    uint16_t ra = *(uint16_t*)&xa, rb = *(uint16_t*)&xb;
    return (uint32_t)ra | ((uint32_t)rb << 16);
}
__device__ __forceinline__ uint32_t pkh(float a, float b) {     // fp16x2 pack (GEMM path)
    __half2 h = __floats2half2_rn(a, b);
    return *(uint32_t*)&h;
}
__device__ __forceinline__ float bf_lo(uint32_t v) { return __uint_as_float(v << 16); }
__device__ __forceinline__ float bf_hi(uint32_t v) { return __uint_as_float(v & 0xffff0000u); }

__device__ __forceinline__ void mma16816(float* c, const uint32_t* a, const uint32_t* b) {
    asm volatile(
        "mma.sync.aligned.m16n8k16.row.col.f32.bf16.bf16.f32 "
        "{%0,%1,%2,%3}, {%4,%5,%6,%7}, {%8,%9}, {%0,%1,%2,%3};\n"
        : "+f"(c[0]), "+f"(c[1]), "+f"(c[2]), "+f"(c[3])
        : "r"(a[0]), "r"(a[1]), "r"(a[2]), "r"(a[3]), "r"(b[0]), "r"(b[1]));
}
__device__ __forceinline__ void mma16816h(float* c, const uint32_t* a, const uint32_t* b) {
    asm volatile(
        "mma.sync.aligned.m16n8k16.row.col.f32.f16.f16.f32 "
        "{%0,%1,%2,%3}, {%4,%5,%6,%7}, {%8,%9}, {%0,%1,%2,%3};\n"
        : "+f"(c[0]), "+f"(c[1]), "+f"(c[2]), "+f"(c[3])
        : "r"(a[0]), "r"(a[1]), "r"(a[2]), "r"(a[3]), "r"(b[0]), "r"(b[1]));
}
__device__ __forceinline__ void ldmx4(uint32_t* r, uint32_t addr) {
    asm volatile("ldmatrix.sync.aligned.m8n8.x4.shared.b16 {%0,%1,%2,%3}, [%4];"
        : "=r"(r[0]), "=r"(r[1]), "=r"(r[2]), "=r"(r[3]) : "r"(addr));
}
#define CP_ASYNC16(dst, src) asm volatile("cp.async.ca.shared.global [%0], [%1], 16;" :: "r"(dst), "l"(src))
#define CP_COMMIT()          asm volatile("cp.async.commit_group;" ::: "memory")
#define CP_WAIT(n)           asm volatile("cp.async.wait_group %0;" :: "n"(n) : "memory")

// ---------------- weight prep (3 launches so slot 4 = qkv GEMM in ncu) ----------------
__global__ void wprep_qkvw_kernel(const float* __restrict__ qkvw)
{
    int i = blockIdx.x * 256 + threadIdx.x;
    if (i < C3 * KDIM) {
        int n = i / KDIM, k = i % KDIM;
        float v = qkvw[(size_t)k * C3 + n];
        __half h = __float2half_rn(v);
        g_wqkv_h[i] = h;
        g_wqkv_l[i] = __float2half_rn(v - __half2float(h));
    }
}
__global__ void wprep_projw_kernel(const float* __restrict__ projw)
{
    int i = blockIdx.x * 256 + threadIdx.x;
    if (i < NC * KDIM) {
        int n = i / KDIM, k = i % KDIM;
        float v = projw[(size_t)k * NC + n];
        __half h = __float2half_rn(v);
        g_wproj_h[i] = h;
        g_wproj_l[i] = __float2half_rn(v - __half2float(h));
    }
}
__global__ void zero_kernel()
{
    int i = blockIdx.x * 256 + threadIdx.x;
    if (i < BNT * CH * CH) g_attn[i] = 0.f;
    if (i < BNT * CH) { g_ssq_q[i] = 0.f; g_ssq_k[i] = 0.f; }
}

// ---------------- fp16 2-term GEMM: [M,192]fp32 x W[N,192]fp16(hi/lo) -> [M,N]fp32 ----------------
// D = A16*Bh + A16*Bl (A rounded to fp16; B hi+lo exact). CTA tile 128x64, 256 thr,
// 8 warps (4M x 2N), warp tile 32x32. smem 102400 -> 2 CTAs/SM.
#define ASTRIDE 200
#define ROWB    (ASTRIDE * 2)          // 400 bytes per row
#define OFF_A   0                       // 128 * 400 = 51200
#define OFF_BH  (128 * ROWB)            // 51200
#define OFF_BL  (128 * ROWB + 64 * ROWB)// 76800
#define GEMM_SMEM (128 * ROWB + 2 * 64 * ROWB)   // 102400

__global__ __launch_bounds__(256, 2) void gemm_fp16_split(
    const float* __restrict__ A, const __half* __restrict__ Wh,
    const __half* __restrict__ Wl, float* __restrict__ Cout, int Ntot)
{
    extern __shared__ char smem[];
    const uint32_t sbase = smem_u32(smem);
    const uint32_t sA  = sbase + OFF_A;
    const uint32_t sBh = sbase + OFF_BH;
    const uint32_t sBl = sbase + OFF_BL;

    const int t = threadIdx.x;
    const int warp = t >> 5, lane = t & 31;
    const int grp = lane >> 2, tig = lane & 3;
    const int warpM = warp >> 1, warpN = warp & 1;      // 4 x 2
    const size_t m0 = (size_t)blockIdx.x * 128;
    const int nChunks = Ntot >> 6;

    const uint32_t aOff = (uint32_t)(warpM * 32 + (lane & 15)) * ROWB + ((lane >> 4) * 16);
    const uint32_t bOff = (uint32_t)(warpN * 32 + ((lane >> 4) * 8) + (lane & 7)) * ROWB
                          + (((lane >> 3) & 1) * 16);

    // ---- issue B chunk 0 load ----
    {
        const uint4* bh = (const uint4*)Wh;
        const uint4* bl = (const uint4*)Wl;
#pragma unroll
        for (int i = t; i < 1536; i += 256) {          // 64 rows * 24 uint4
            int row = i / 24, cb = (i % 24) * 16;
            uint32_t o = (uint32_t)row * ROWB + cb;
            CP_ASYNC16(sBh + o, bh + i);
            CP_ASYNC16(sBl + o, bl + i);
        }
        CP_COMMIT();
    }
    // ---- A: 128 rows fp32 -> single fp16 plane (overlaps B0 load) ----
    {
        int row = t >> 1, half = t & 1;
        const float4* ar = (const float4*)(A + (m0 + row) * KDIM + half * 96);
        __half* ap = (__half*)(smem + OFF_A) + row * ASTRIDE + half * 96;
#pragma unroll
        for (int j = 0; j < 24; j++) {
            float4 v = ar[j];
            *(uint32_t*)(ap + j * 4)     = pkh(v.x, v.y);
            *(uint32_t*)(ap + j * 4 + 2) = pkh(v.z, v.w);
        }
    }
    CP_WAIT(0);
    __syncthreads();

    float c[2][4][4];

    for (int nc = 0; nc < nChunks; nc++) {
#pragma unroll
        for (int mi = 0; mi < 2; mi++)
#pragma unroll
            for (int nj = 0; nj < 4; nj++)
#pragma unroll
                for (int j = 0; j < 4; j++) c[mi][nj][j] = 0.f;

#pragma unroll
        for (int ks = 0; ks < 12; ks++) {
            const uint32_t k32 = ks * 32;
            uint32_t a0[4], a1[4], bh0[4], bh1[4], bl0[4], bl1[4];
            ldmx4(a0, sA + aOff + k32);
            ldmx4(a1, sA + aOff + 16 * ROWB + k32);
            ldmx4(bh0, sBh + bOff + k32);
            ldmx4(bh1, sBh + bOff + 16 * ROWB + k32);
            ldmx4(bl0, sBl + bOff + k32);
            ldmx4(bl1, sBl + bOff + 16 * ROWB + k32);
            // sweep 1: A * Bh (accumulator reuse distance 8)
            mma16816h(c[0][0], a0, &bh0[0]);
            mma16816h(c[0][1], a0, &bh0[2]);
            mma16816h(c[0][2], a0, &bh1[0]);
            mma16816h(c[0][3], a0, &bh1[2]);
            mma16816h(c[1][0], a1, &bh0[0]);
            mma16816h(c[1][1], a1, &bh0[2]);
            mma16816h(c[1][2], a1, &bh1[0]);
            mma16816h(c[1][3], a1, &bh1[2]);
            // sweep 2: A * Bl
            mma16816h(c[0][0], a0, &bl0[0]);
            mma16816h(c[0][1], a0, &bl0[2]);
            mma16816h(c[0][2], a0, &bl1[0]);
            mma16816h(c[0][3], a0, &bl1[2]);
            mma16816h(c[1][0], a1, &bl0[0]);
            mma16816h(c[1][1], a1, &bl0[2]);
            mma16816h(c[1][2], a1, &bl1[0]);
            mma16816h(c[1][3], a1, &bl1[2]);
        }
        __syncthreads();   // all warps done reading this B chunk

        // issue next B chunk load (overlaps epilogue stores; partner CTA hides rest)
        if (nc + 1 < nChunks) {
            const uint4* bh = (const uint4*)(Wh + (size_t)(nc + 1) * 64 * KDIM);
            const uint4* bl = (const uint4*)(Wl + (size_t)(nc + 1) * 64 * KDIM);
#pragma unroll
            for (int i = t; i < 1536; i += 256) {
                int row = i / 24, cb = (i % 24) * 16;
                uint32_t o = (uint32_t)row * ROWB + cb;
                CP_ASYNC16(sBh + o, bh + i);
                CP_ASYNC16(sBl + o, bl + i);
            }
            CP_COMMIT();
        }

        // epilogue: store 128x64 chunk
        const int n0 = nc * 64;
#pragma unroll
        for (int mi = 0; mi < 2; mi++) {
            size_t row = m0 + warpM * 32 + mi * 16 + grp;
#pragma unroll
            for (int nj = 0; nj < 4; nj++) {
                int col = n0 + warpN * 32 + nj * 8 + tig * 2;
                *(float2*)(Cout + row * Ntot + col) = make_float2(c[mi][nj][0], c[mi][nj][1]);
                *(float2*)(Cout + (row + 8) * Ntot + col) = make_float2(c[mi][nj][2], c[mi][nj][3]);
            }
        }
        CP_WAIT(0);
        __syncthreads();
    }
}

// ---------------- depthwise 3x3 SAME + split (naive/coalesced; q/k -> bf16 hi/lo) ----------------
__global__ __launch_bounds__(256) void dwconv_split_kernel(const float* __restrict__ w)
{
    int gid = blockIdx.x * 256 + threadIdx.x;
    int c4 = gid % 144;
    int p = gid / 144;
    int x = p % WW;
    int y = (p / WW) % HH;
    int b = p / HW;
    int c = c4 * 4;

    float4 acc = make_float4(0.f, 0.f, 0.f, 0.f);
#pragma unroll
    for (int dy = -1; dy <= 1; dy++) {
        int yy = y + dy;
        if (yy < 0 || yy >= HH) continue;
#pragma unroll
        for (int dx = -1; dx <= 1; dx++) {
            int xx = x + dx;
            if (xx < 0 || xx >= WW) continue;
            const float4 iv = *(const float4*)(g_qkv + ((size_t)((b * HH + yy) * WW + xx)) * C3 + c);
            const float4 wv = *(const float4*)(w + (size_t)((dy + 1) * 3 + (dx + 1)) * C3 + c);
            acc.x = fmaf(iv.x, wv.x, acc.x);
            acc.y = fmaf(iv.y, wv.y, acc.y);
            acc.z = fmaf(iv.z, wv.z, acc.z);
            acc.w = fmaf(iv.w, wv.w, acc.w);
        }
    }
    if (c < NC) {
        int cc = c;
        *(uint2*)&g_qh[(size_t)p * NC + cc] = make_uint2(pk_hi(acc.x, acc.y), pk_hi(acc.z, acc.w));
        *(uint2*)&g_ql[(size_t)p * NC + cc] = make_uint2(pk_lo(acc.x, acc.y), pk_lo(acc.z, acc.w));
    } else if (c < 2 * NC) {
        int cc = c - NC;
        *(uint2*)&g_kh[(size_t)p * NC + cc] = make_uint2(pk_hi(acc.x, acc.y), pk_hi(acc.z, acc.w));
        *(uint2*)&g_kl[(size_t)p * NC + cc] = make_uint2(pk_lo(acc.x, acc.y), pk_lo(acc.z, acc.w));
    } else {
        int cc = c - 2 * NC;
        *(float4*)&g_v[(size_t)p * NC + cc] = acc;
    }
}

// ---------------- QK^T via mma.sync bf16-split + fused ssq ----------------
#define QK_PLANE 25344                     // 48 rows * 528 bytes
#define QK_SMEM  (4 * QK_PLANE)            // 101376

__global__ __launch_bounds__(256) void qk_mma_kernel()
{
    extern __shared__ char qsm[];
    const uint32_t sb = smem_u32(qsm);
    const int t = threadIdx.x, lane = t & 31, warp = t >> 5;
    const int grp = lane >> 2, tig = lane & 3;
    const int bn = blockIdx.x;
    const int sbase0 = blockIdx.y * 2048;

    const uint32_t aAddr = sb + (uint32_t)(lane & 15) * 528 + warp * 64 + ((lane >> 4) * 16);
    const uint32_t bAddr = sb + (uint32_t)(((lane >> 4) * 8) + (lane & 7)) * 528 + warp * 64
                           + (((lane >> 3) & 1) * 16);

    float c[3][6][4];
#pragma unroll
    for (int mi = 0; mi < 3; mi++)
#pragma unroll
        for (int nj = 0; nj < 6; nj++)
#pragma unroll
            for (int j = 0; j < 4; j++) c[mi][nj][j] = 0.f;
    float sq[3][2] = {{0.f,0.f},{0.f,0.f},{0.f,0.f}};
    float sk[3][2] = {{0.f,0.f},{0.f,0.f},{0.f,0.f}};

    for (int stage = 0; stage < 8; stage++) {
        const int sbase = sbase0 + stage * 256;
        const __nv_bfloat16* gp0 = g_qh; const __nv_bfloat16* gp1 = g_ql;
        const __nv_bfloat16* gp2 = g_kh; const __nv_bfloat16* gp3 = g_kl;
#pragma unroll
        for (int pl = 0; pl < 4; pl++) {
            const __nv_bfloat16* gp = (pl == 0) ? gp0 : (pl == 1) ? gp1 : (pl == 2) ? gp2 : gp3;
            uint32_t sp = sb + pl * QK_PLANE;
            for (int i = t; i < 1536; i += 256) {
                int r = i >> 5, seg = i & 31;
                const void* src = gp + (((size_t)(bn * 48 + r)) << 14) + sbase + seg * 8;
                CP_ASYNC16(sp + (uint32_t)r * 528 + seg * 16, src);
            }
        }
        CP_COMMIT();
        CP_WAIT(0);
        __syncthreads();

#pragma unroll
        for (int ks = 0; ks < 2; ks++) {
            const uint32_t kb = ks * 32;
            uint32_t ah[3][4], al[3][4], bh[3][4], bl[3][4];
#pragma unroll
            for (int mi = 0; mi < 3; mi++) {
                ldmx4(ah[mi], aAddr + (uint32_t)(mi * 16) * 528 + kb);
                ldmx4(al[mi], aAddr + QK_PLANE + (uint32_t)(mi * 16) * 528 + kb);
            }
#pragma unroll
            for (int pj = 0; pj < 3; pj++) {
                ldmx4(bh[pj], bAddr + 2 * QK_PLANE + (uint32_t)(pj * 16) * 528 + kb);
                ldmx4(bl[pj], bAddr + 3 * QK_PLANE + (uint32_t)(pj * 16) * 528 + kb);
            }
#pragma unroll
            for (int mi = 0; mi < 3; mi++)
#pragma unroll
                for (int r = 0; r < 4; r++) {
                    float f0 = bf_lo(ah[mi][r]) + bf_lo(al[mi][r]);
                    float f1 = bf_hi(ah[mi][r]) + bf_hi(al[mi][r]);
                    sq[mi][r & 1] = fmaf(f0, f0, fmaf(f1, f1, sq[mi][r & 1]));
                }
#pragma unroll
            for (int pj = 0; pj < 3; pj++)
#pragma unroll
                for (int r = 0; r < 4; r++) {
                    float f0 = bf_lo(bh[pj][r]) + bf_lo(bl[pj][r]);
                    float f1 = bf_hi(bh[pj][r]) + bf_hi(bl[pj][r]);
                    sk[pj][r >> 1] = fmaf(f0, f0, fmaf(f1, f1, sk[pj][r >> 1]));
                }
#pragma unroll
            for (int mi = 0; mi < 3; mi++)
#pragma unroll
                for (int pj = 0; pj < 3; pj++) {
                    mma16816(c[mi][2 * pj],     ah[mi], &bh[pj][0]);
                    mma16816(c[mi][2 * pj + 1], ah[mi], &bh[pj][2]);
                }
#pragma unroll
            for (int mi = 0; mi < 3; mi++)
#pragma unroll
                for (int pj = 0; pj < 3; pj++) {
                    mma16816(c[mi][2 * pj],     ah[mi], &bl[pj][0]);
                    mma16816(c[mi][2 * pj + 1], ah[mi], &bl[pj][2]);
                }
#pragma unroll
            for (int mi = 0; mi < 3; mi++)
#pragma unroll
                for (int pj = 0; pj < 3; pj++) {
                    mma16816(c[mi][2 * pj],     al[mi], &bh[pj][0]);
                    mma16816(c[mi][2 * pj + 1], al[mi], &bh[pj][2]);
                }
        }
        __syncthreads();
    }

    float* attn_s = (float*)qsm;
    float* ssq_qs = attn_s + 2304;
    float* ssq_ks = ssq_qs + 48;
    for (int i = t; i < 2400; i += 256) attn_s[i] = 0.f;
    __syncthreads();

#pragma unroll
    for (int mi = 0; mi < 3; mi++)
#pragma unroll
        for (int nj = 0; nj < 6; nj++) {
            int row = mi * 16 + grp, col = nj * 8 + tig * 2;
            atomicAdd(&attn_s[row * 48 + col],           c[mi][nj][0]);
            atomicAdd(&attn_s[row * 48 + col + 1],       c[mi][nj][1]);
            atomicAdd(&attn_s[(row + 8) * 48 + col],     c[mi][nj][2]);
            atomicAdd(&attn_s[(row + 8) * 48 + col + 1], c[mi][nj][3]);
        }
#pragma unroll
    for (int mi = 0; mi < 3; mi++)
#pragma unroll
        for (int h = 0; h < 2; h++) {
            float v = sq[mi][h];
            v += __shfl_xor_sync(~0u, v, 1);
            v += __shfl_xor_sync(~0u, v, 2);
            if (tig == 0) atomicAdd(&ssq_qs[mi * 16 + h * 8 + grp], v);
            float u = sk[mi][h];
            u += __shfl_xor_sync(~0u, u, 1);
            u += __shfl_xor_sync(~0u, u, 2);
            if (tig == 0) atomicAdd(&ssq_ks[mi * 16 + h * 8 + grp], u);
        }
    __syncthreads();

    for (int i = t; i < 2304; i += 256) atomicAdd(&g_attn[bn * 2304 + i], attn_s[i]);
    if (t < 48) atomicAdd(&g_ssq_q[bn * 48 + t], ssq_qs[t]);
    else if (t < 96) atomicAdd(&g_ssq_k[bn * 48 + t - 48], ssq_ks[t - 48]);
}

// ---------------- softmax with l2-norm scaling + temperature ----------------
__global__ void softmax48_kernel(const float* __restrict__ temp)
{
    int row = blockIdx.x;
    int bn = row / CH;
    int n = bn & (HEADS - 1);
    int l = threadIdx.x;
    float tf = temp[n];
    float iq = rsqrtf(fmaxf(g_ssq_q[row], 1e-12f));
    float* arow = g_attn + (size_t)row * CH;

    float ik0 = rsqrtf(fmaxf(g_ssq_k[bn * CH + l], 1e-12f));
    float v0 = arow[l] * iq * ik0 * tf;
    float v1 = -3.0e38f;
    if (l < 16) {
        float ik1 = rsqrtf(fmaxf(g_ssq_k[bn * CH + l + 32], 1e-12f));
        v1 = arow[l + 32] * iq * ik1 * tf;
    }
    float m = fmaxf(v0, v1);
#pragma unroll
    for (int o = 16; o > 0; o >>= 1) m = fmaxf(m, __shfl_xor_sync(~0u, m, o));
    float e0 = expf(v0 - m);
    float e1 = (l < 16) ? expf(v1 - m) : 0.f;
    float s = e0 + e1;
#pragma unroll
    for (int o = 16; o > 0; o >>= 1) s += __shfl_xor_sync(~0u, s, o);
    float inv = 1.f / s;
    arow[l] = e0 * inv;
    if (l < 16) arow[l + 32] = e1 * inv;
}

// ---------------- out = attn @ V ----------------
__global__ __launch_bounds__(256) void av_kernel()
{
    int bn = blockIdx.x;
    int s2 = blockIdx.y * 256 + threadIdx.x;

    __shared__ float As[CH * CH];
    for (int f = threadIdx.x; f < CH * CH; f += 256) As[f] = g_attn[bn * CH * CH + f];
    __syncthreads();

    const float2* vb = (const float2*)(g_v + (size_t)bn * CH * HW) + s2;
    float2 vr[CH];
#pragma unroll
    for (int e = 0; e < CH; e++) vr[e] = vb[(size_t)e * (HW / 2)];

    float2* ob = (float2*)(g_o + (size_t)bn * CH * HW) + s2;
    for (int d = 0; d < CH; d++) {
        float2 a = make_float2(0.f, 0.f);
#pragma unroll
        for (int e = 0; e < CH; e++) {
            float w = As[d * CH + e];
            a.x = fmaf(w, vr[e].x, a.x);
            a.y = fmaf(w, vr[e].y, a.y);
        }
        ob[(size_t)d * (HW / 2)] = a;
    }
}

// ---------------- launch ----------------
extern "C" void kernel_launch(void* const* d_in, const int* in_sizes, int n_in,
                              void* d_out, int out_size)
{
    const float* x      = (const float*)d_in[0];
    const float* qkv_w  = (const float*)d_in[1];
    const float* dw_w   = (const float*)d_in[2];
    const float* proj_w = (const float*)d_in[3];
    const float* temp   = (const float*)d_in[4];
    float* out = (float*)d_out;

    float *qkv_buf, *o_buf;
    cudaGetSymbolAddress((void**)&qkv_buf, g_qkv);
    cudaGetSymbolAddress((void**)&o_buf, g_o);
    __half *wqh, *wql, *wph, *wpl;
    cudaGetSymbolAddress((void**)&wqh, g_wqkv_h);
    cudaGetSymbolAddress((void**)&wql, g_wqkv_l);
    cudaGetSymbolAddress((void**)&wph, g_wproj_h);
    cudaGetSymbolAddress((void**)&wpl, g_wproj_l);

    cudaFuncSetAttribute(gemm_fp16_split, cudaFuncAttributeMaxDynamicSharedMemorySize, GEMM_SMEM);
    cudaFuncSetAttribute(qk_mma_kernel, cudaFuncAttributeMaxDynamicSharedMemorySize, QK_SMEM);

    const int M = NB * HW;

    // launches 1-3: prep (slot 4 = qkv GEMM gets profiled)
    wprep_qkvw_kernel<<<(C3 * KDIM + 255) / 256, 256>>>(qkv_w);
    wprep_projw_kernel<<<(NC * KDIM + 255) / 256, 256>>>(proj_w);
    zero_kernel<<<(BNT * CH * CH + 255) / 256, 256>>>();

    // 4) qkv = x @ qkv_w   <-- profiled slot
    gemm_fp16_split<<<M / 128, 256, GEMM_SMEM>>>(x, wqh, wql, qkv_buf, C3);

    // 5) depthwise 3x3 + split
    dwconv_split_kernel<<<(NB * HW * (C3 / 4)) / 256, 256>>>(dw_w);

    // 6) QK^T (tensor cores) + fused square sums
    qk_mma_kernel<<<dim3(BNT, 8), 256, QK_SMEM>>>();

    // 7) scale + softmax
    softmax48_kernel<<<BNT * CH, 32>>>(temp);

    // 8) out = attn @ V
    av_kernel<<<dim3(BNT, HW / 512), 256>>>();

    // 9) projection
    gemm_fp16_split<<<M / 128, 256, GEMM_SMEM>>>(o_buf, wph, wpl, out, NC);
}

// round 12
// speedup vs baseline: 1.0814x; 1.0791x over previous
#include <cuda_runtime.h>
#include <cuda_bf16.h>
#include <cuda_fp16.h>
#include <math.h>
#include <stdint.h>

#define NB 8
#define HH 128
#define WW 128
#define NC 192
#define C3 576
#define HEADS 4
#define CH 48
#define HW 16384
#define BNT 32
#define KDIM 192

// ---------------- scratch ----------------
__device__ __half g_qkv_h[(size_t)NB * HW * C3];      // qkv intermediate, fp16
__device__ __nv_bfloat16 g_qh[(size_t)NB * HW * NC];
__device__ __nv_bfloat16 g_ql[(size_t)NB * HW * NC];
__device__ __nv_bfloat16 g_kh[(size_t)NB * HW * NC];
__device__ __nv_bfloat16 g_kl[(size_t)NB * HW * NC];
__device__ __half g_v_h[(size_t)NB * HW * NC];        // v, fp16
__device__ __half g_o_h[(size_t)NB * HW * NC];        // attn@V output, fp16
__device__ float g_attn[BNT * CH * CH];
__device__ float g_ssq_q[BNT * CH];
__device__ float g_ssq_k[BNT * CH];
// GEMM weights: fp16 hi/lo, [N][K]
__device__ __half g_wqkv_h[C3 * KDIM];
__device__ __half g_wqkv_l[C3 * KDIM];
__device__ __half g_wproj_h[NC * KDIM];
__device__ __half g_wproj_l[NC * KDIM];

// ---------------- helpers ----------------
__device__ __forceinline__ uint32_t smem_u32(const void* p) {
    uint32_t a;
    asm("{ .reg .u64 t; cvta.to.shared.u64 t, %1; cvt.u32.u64 %0, t; }" : "=r"(a) : "l"(p));
    return a;
}
__device__ __forceinline__ uint32_t pk_hi(float a, float b) {   // bf16 pack (q/k path)
    __nv_bfloat16 ha = __float2bfloat16(a), hb = __float2bfloat16(b);
    uint16_t ra = *(uint16_t*)&ha, rb = *(uint16_t*)&hb;
    return (uint32_t)ra | ((uint32_t)rb << 16);
}
__device__ __forceinline__ uint32_t pk_lo(float a, float b) {
    __nv_bfloat16 ha = __float2bfloat16(a), hb = __float2bfloat16(b);
    float la = a - __bfloat162float(ha), lb = b - __bfloat162float(hb);
    __nv_bfloat16 xa = __float2bfloat16(la), xb = __float2bfloat16(lb);
    uint16_t ra = *(uint16_t*)&xa, rb = *(uint16_t*)&xb;
    return (uint32_t)ra | ((uint32_t)rb << 16);
}
__device__ __forceinline__ uint32_t pkh(float a, float b) {     // fp16x2 pack
    __half2 h = __floats2half2_rn(a, b);
    return *(uint32_t*)&h;
}
__device__ __forceinline__ float bf_lo(uint32_t v) { return __uint_as_float(v << 16); }
__device__ __forceinline__ float bf_hi(uint32_t v) { return __uint_as_float(v & 0xffff0000u); }

__device__ __forceinline__ void mma16816(float* c, const uint32_t* a, const uint32_t* b) {
    asm volatile(
        "mma.sync.aligned.m16n8k16.row.col.f32.bf16.bf16.f32 "
        "{%0,%1,%2,%3}, {%4,%5,%6,%7}, {%8,%9}, {%0,%1,%2,%3};\n"
        : "+f"(c[0]), "+f"(c[1]), "+f"(c[2]), "+f"(c[3])
        : "r"(a[0]), "r"(a[1]), "r"(a[2]), "r"(a[3]), "r"(b[0]), "r"(b[1]));
}
__device__ __forceinline__ void mma16816h(float* c, const uint32_t* a, const uint32_t* b) {
    asm volatile(
        "mma.sync.aligned.m16n8k16.row.col.f32.f16.f16.f32 "
        "{%0,%1,%2,%3}, {%4,%5,%6,%7}, {%8,%9}, {%0,%1,%2,%3};\n"
        : "+f"(c[0]), "+f"(c[1]), "+f"(c[2]), "+f"(c[3])
        : "r"(a[0]), "r"(a[1]), "r"(a[2]), "r"(a[3]), "r"(b[0]), "r"(b[1]));
}
__device__ __forceinline__ void ldmx4(uint32_t* r, uint32_t addr) {
    asm volatile("ldmatrix.sync.aligned.m8n8.x4.shared.b16 {%0,%1,%2,%3}, [%4];"
        : "=r"(r[0]), "=r"(r[1]), "=r"(r[2]), "=r"(r[3]) : "r"(addr));
}
#define CP_ASYNC16(dst, src) asm volatile("cp.async.ca.shared.global [%0], [%1], 16;" :: "r"(dst), "l"(src))
#define CP_COMMIT()          asm volatile("cp.async.commit_group;" ::: "memory")
#define CP_WAIT(n)           asm volatile("cp.async.wait_group %0;" :: "n"(n) : "memory")

// ---------------- weight prep (3 launches so slot 4 = qkv GEMM in ncu) ----------------
__global__ void wprep_qkvw_kernel(const float* __restrict__ qkvw)
{
    int i = blockIdx.x * 256 + threadIdx.x;
    if (i < C3 * KDIM) {
        int n = i / KDIM, k = i % KDIM;
        float v = qkvw[(size_t)k * C3 + n];
        __half h = __float2half_rn(v);
        g_wqkv_h[i] = h;
        g_wqkv_l[i] = __float2half_rn(v - __half2float(h));
    }
}
__global__ void wprep_projw_kernel(const float* __restrict__ projw)
{
    int i = blockIdx.x * 256 + threadIdx.x;
    if (i < NC * KDIM) {
        int n = i / KDIM, k = i % KDIM;
        float v = projw[(size_t)k * NC + n];
        __half h = __float2half_rn(v);
        g_wproj_h[i] = h;
        g_wproj_l[i] = __float2half_rn(v - __half2float(h));
    }
}
__global__ void zero_kernel()
{
    int i = blockIdx.x * 256 + threadIdx.x;
    if (i < BNT * CH * CH) g_attn[i] = 0.f;
    if (i < BNT * CH) { g_ssq_q[i] = 0.f; g_ssq_k[i] = 0.f; }
}

// ---------------- fp16 2-term GEMM (templated A input / output type) ----------------
// D = A16*Bh + A16*Bl. CTA tile 128x64, 256 thr, 8 warps (4M x 2N), warp tile 32x32.
// smem 102400 -> 2 CTAs/SM.
// AHALF: A already fp16 in gmem (pure cp.async); else fp32 with convert.
// OUTHALF: store __half output; else fp32.
#define ASTRIDE 200
#define ROWB    (ASTRIDE * 2)          // 400 bytes per row
#define OFF_A   0                       // 128 * 400 = 51200
#define OFF_BH  (128 * ROWB)            // 51200
#define OFF_BL  (128 * ROWB + 64 * ROWB)// 76800
#define GEMM_SMEM (128 * ROWB + 2 * 64 * ROWB)   // 102400

template<bool AHALF, bool OUTHALF>
__global__ __launch_bounds__(256, 2) void gemm_fp16_split(
    const void* __restrict__ Aptr, const __half* __restrict__ Wh,
    const __half* __restrict__ Wl, void* __restrict__ Coutp, int Ntot)
{
    extern __shared__ char smem[];
    const uint32_t sbase = smem_u32(smem);
    const uint32_t sA  = sbase + OFF_A;
    const uint32_t sBh = sbase + OFF_BH;
    const uint32_t sBl = sbase + OFF_BL;

    const int t = threadIdx.x;
    const int warp = t >> 5, lane = t & 31;
    const int grp = lane >> 2, tig = lane & 3;
    const int warpM = warp >> 1, warpN = warp & 1;      // 4 x 2
    const size_t m0 = (size_t)blockIdx.x * 128;
    const int nChunks = Ntot >> 6;

    const uint32_t aOff = (uint32_t)(warpM * 32 + (lane & 15)) * ROWB + ((lane >> 4) * 16);
    const uint32_t bOff = (uint32_t)(warpN * 32 + ((lane >> 4) * 8) + (lane & 7)) * ROWB
                          + (((lane >> 3) & 1) * 16);

    // ---- issue B chunk 0 load ----
    {
        const uint4* bh = (const uint4*)Wh;
        const uint4* bl = (const uint4*)Wl;
#pragma unroll
        for (int i = t; i < 1536; i += 256) {          // 64 rows * 24 uint4
            int row = i / 24, cb = (i % 24) * 16;
            uint32_t o = (uint32_t)row * ROWB + cb;
            CP_ASYNC16(sBh + o, bh + i);
            CP_ASYNC16(sBl + o, bl + i);
        }
        CP_COMMIT();
    }
    // ---- A tile ----
    if (AHALF) {
        // fp16 rows: pure async copy, 128 rows * 24 uint4
        const __half* Ah = (const __half*)Aptr;
#pragma unroll
        for (int i = t; i < 3072; i += 256) {
            int row = i / 24, seg = i % 24;
            const uint4* src = (const uint4*)(Ah + (m0 + row) * KDIM) + seg;
            CP_ASYNC16(sA + (uint32_t)row * ROWB + seg * 16, src);
        }
        CP_COMMIT();
    } else {
        const float* Af = (const float*)Aptr;
        int row = t >> 1, half = t & 1;
        const float4* ar = (const float4*)(Af + (m0 + row) * KDIM + half * 96);
        __half* ap = (__half*)(smem + OFF_A) + row * ASTRIDE + half * 96;
#pragma unroll
        for (int j = 0; j < 24; j++) {
            float4 v = ar[j];
            *(uint32_t*)(ap + j * 4)     = pkh(v.x, v.y);
            *(uint32_t*)(ap + j * 4 + 2) = pkh(v.z, v.w);
        }
    }
    CP_WAIT(0);
    __syncthreads();

    float c[2][4][4];

    for (int nc = 0; nc < nChunks; nc++) {
#pragma unroll
        for (int mi = 0; mi < 2; mi++)
#pragma unroll
            for (int nj = 0; nj < 4; nj++)
#pragma unroll
                for (int j = 0; j < 4; j++) c[mi][nj][j] = 0.f;

#pragma unroll
        for (int ks = 0; ks < 12; ks++) {
            const uint32_t k32 = ks * 32;
            uint32_t a0[4], a1[4], bh0[4], bh1[4], bl0[4], bl1[4];
            ldmx4(a0, sA + aOff + k32);
            ldmx4(a1, sA + aOff + 16 * ROWB + k32);
            ldmx4(bh0, sBh + bOff + k32);
            ldmx4(bh1, sBh + bOff + 16 * ROWB + k32);
            ldmx4(bl0, sBl + bOff + k32);
            ldmx4(bl1, sBl + bOff + 16 * ROWB + k32);
            // sweep 1: A * Bh (accumulator reuse distance 8)
            mma16816h(c[0][0], a0, &bh0[0]);
            mma16816h(c[0][1], a0, &bh0[2]);
            mma16816h(c[0][2], a0, &bh1[0]);
            mma16816h(c[0][3], a0, &bh1[2]);
            mma16816h(c[1][0], a1, &bh0[0]);
            mma16816h(c[1][1], a1, &bh0[2]);
            mma16816h(c[1][2], a1, &bh1[0]);
            mma16816h(c[1][3], a1, &bh1[2]);
            // sweep 2: A * Bl
            mma16816h(c[0][0], a0, &bl0[0]);
            mma16816h(c[0][1], a0, &bl0[2]);
            mma16816h(c[0][2], a0, &bl1[0]);
            mma16816h(c[0][3], a0, &bl1[2]);
            mma16816h(c[1][0], a1, &bl0[0]);
            mma16816h(c[1][1], a1, &bl0[2]);
            mma16816h(c[1][2], a1, &bl1[0]);
            mma16816h(c[1][3], a1, &bl1[2]);
        }
        __syncthreads();   // all warps done reading this B chunk

        // issue next B chunk load (overlaps epilogue stores; partner CTA hides rest)
        if (nc + 1 < nChunks) {
            const uint4* bh = (const uint4*)(Wh + (size_t)(nc + 1) * 64 * KDIM);
            const uint4* bl = (const uint4*)(Wl + (size_t)(nc + 1) * 64 * KDIM);
#pragma unroll
            for (int i = t; i < 1536; i += 256) {
                int row = i / 24, cb = (i % 24) * 16;
                uint32_t o = (uint32_t)row * ROWB + cb;
                CP_ASYNC16(sBh + o, bh + i);
                CP_ASYNC16(sBl + o, bl + i);
            }
            CP_COMMIT();
        }

        // epilogue: store 128x64 chunk
        const int n0 = nc * 64;
#pragma unroll
        for (int mi = 0; mi < 2; mi++) {
            size_t row = m0 + warpM * 32 + mi * 16 + grp;
#pragma unroll
            for (int nj = 0; nj < 4; nj++) {
                int col = n0 + warpN * 32 + nj * 8 + tig * 2;
                if (OUTHALF) {
                    __half* co = (__half*)Coutp;
                    *(uint32_t*)(co + row * Ntot + col)       = pkh(c[mi][nj][0], c[mi][nj][1]);
                    *(uint32_t*)(co + (row + 8) * Ntot + col) = pkh(c[mi][nj][2], c[mi][nj][3]);
                } else {
                    float* co = (float*)Coutp;
                    *(float2*)(co + row * Ntot + col) = make_float2(c[mi][nj][0], c[mi][nj][1]);
                    *(float2*)(co + (row + 8) * Ntot + col) = make_float2(c[mi][nj][2], c[mi][nj][3]);
                }
            }
        }
        CP_WAIT(0);
        __syncthreads();
    }
}

// ---------------- depthwise 3x3 SAME + split (fp16 input; q/k -> bf16 hi/lo, v -> fp16) ----------------
__global__ __launch_bounds__(256) void dwconv_split_kernel(const float* __restrict__ w)
{
    int gid = blockIdx.x * 256 + threadIdx.x;
    int c4 = gid % 144;
    int p = gid / 144;
    int x = p % WW;
    int y = (p / WW) % HH;
    int b = p / HW;
    int c = c4 * 4;

    float4 acc = make_float4(0.f, 0.f, 0.f, 0.f);
#pragma unroll
    for (int dy = -1; dy <= 1; dy++) {
        int yy = y + dy;
        if (yy < 0 || yy >= HH) continue;
#pragma unroll
        for (int dx = -1; dx <= 1; dx++) {
            int xx = x + dx;
            if (xx < 0 || xx >= WW) continue;
            const __half2* iv2 = (const __half2*)(g_qkv_h + ((size_t)((b * HH + yy) * WW + xx)) * C3 + c);
            float2 p0 = __half22float2(iv2[0]);
            float2 p1 = __half22float2(iv2[1]);
            const float4 wv = *(const float4*)(w + (size_t)((dy + 1) * 3 + (dx + 1)) * C3 + c);
            acc.x = fmaf(p0.x, wv.x, acc.x);
            acc.y = fmaf(p0.y, wv.y, acc.y);
            acc.z = fmaf(p1.x, wv.z, acc.z);
            acc.w = fmaf(p1.y, wv.w, acc.w);
        }
    }
    if (c < NC) {
        int cc = c;
        *(uint2*)&g_qh[(size_t)p * NC + cc] = make_uint2(pk_hi(acc.x, acc.y), pk_hi(acc.z, acc.w));
        *(uint2*)&g_ql[(size_t)p * NC + cc] = make_uint2(pk_lo(acc.x, acc.y), pk_lo(acc.z, acc.w));
    } else if (c < 2 * NC) {
        int cc = c - NC;
        *(uint2*)&g_kh[(size_t)p * NC + cc] = make_uint2(pk_hi(acc.x, acc.y), pk_hi(acc.z, acc.w));
        *(uint2*)&g_kl[(size_t)p * NC + cc] = make_uint2(pk_lo(acc.x, acc.y), pk_lo(acc.z, acc.w));
    } else {
        int cc = c - 2 * NC;
        *(uint2*)&g_v_h[(size_t)p * NC + cc] = make_uint2(pkh(acc.x, acc.y), pkh(acc.z, acc.w));
    }
}

// ---------------- QK^T via mma.sync bf16-split + fused ssq ----------------
#define QK_PLANE 25344                     // 48 rows * 528 bytes
#define QK_SMEM  (4 * QK_PLANE)            // 101376

__global__ __launch_bounds__(256) void qk_mma_kernel()
{
    extern __shared__ char qsm[];
    const uint32_t sb = smem_u32(qsm);
    const int t = threadIdx.x, lane = t & 31, warp = t >> 5;
    const int grp = lane >> 2, tig = lane & 3;
    const int bn = blockIdx.x;
    const int sbase0 = blockIdx.y * 2048;

    const uint32_t aAddr = sb + (uint32_t)(lane & 15) * 528 + warp * 64 + ((lane >> 4) * 16);
    const uint32_t bAddr = sb + (uint32_t)(((lane >> 4) * 8) + (lane & 7)) * 528 + warp * 64
                           + (((lane >> 3) & 1) * 16);

    float c[3][6][4];
#pragma unroll
    for (int mi = 0; mi < 3; mi++)
#pragma unroll
        for (int nj = 0; nj < 6; nj++)
#pragma unroll
            for (int j = 0; j < 4; j++) c[mi][nj][j] = 0.f;
    float sq[3][2] = {{0.f,0.f},{0.f,0.f},{0.f,0.f}};
    float sk[3][2] = {{0.f,0.f},{0.f,0.f},{0.f,0.f}};

    for (int stage = 0; stage < 8; stage++) {
        const int sbase = sbase0 + stage * 256;
        const __nv_bfloat16* gp0 = g_qh; const __nv_bfloat16* gp1 = g_ql;
        const __nv_bfloat16* gp2 = g_kh; const __nv_bfloat16* gp3 = g_kl;
#pragma unroll
        for (int pl = 0; pl < 4; pl++) {
            const __nv_bfloat16* gp = (pl == 0) ? gp0 : (pl == 1) ? gp1 : (pl == 2) ? gp2 : gp3;
            uint32_t sp = sb + pl * QK_PLANE;
            for (int i = t; i < 1536; i += 256) {
                int r = i >> 5, seg = i & 31;
                const void* src = gp + (((size_t)(bn * 48 + r)) << 14) + sbase + seg * 8;
                CP_ASYNC16(sp + (uint32_t)r * 528 + seg * 16, src);
            }
        }
        CP_COMMIT();
        CP_WAIT(0);
        __syncthreads();

#pragma unroll
        for (int ks = 0; ks < 2; ks++) {
            const uint32_t kb = ks * 32;
            uint32_t ah[3][4], al[3][4], bh[3][4], bl[3][4];
#pragma unroll
            for (int mi = 0; mi < 3; mi++) {
                ldmx4(ah[mi], aAddr + (uint32_t)(mi * 16) * 528 + kb);
                ldmx4(al[mi], aAddr + QK_PLANE + (uint32_t)(mi * 16) * 528 + kb);
            }
#pragma unroll
            for (int pj = 0; pj < 3; pj++) {
                ldmx4(bh[pj], bAddr + 2 * QK_PLANE + (uint32_t)(pj * 16) * 528 + kb);
                ldmx4(bl[pj], bAddr + 3 * QK_PLANE + (uint32_t)(pj * 16) * 528 + kb);
            }
#pragma unroll
            for (int mi = 0; mi < 3; mi++)
#pragma unroll
                for (int r = 0; r < 4; r++) {
                    float f0 = bf_lo(ah[mi][r]) + bf_lo(al[mi][r]);
                    float f1 = bf_hi(ah[mi][r]) + bf_hi(al[mi][r]);
                    sq[mi][r & 1] = fmaf(f0, f0, fmaf(f1, f1, sq[mi][r & 1]));
                }
#pragma unroll
            for (int pj = 0; pj < 3; pj++)
#pragma unroll
                for (int r = 0; r < 4; r++) {
                    float f0 = bf_lo(bh[pj][r]) + bf_lo(bl[pj][r]);
                    float f1 = bf_hi(bh[pj][r]) + bf_hi(bl[pj][r]);
                    sk[pj][r >> 1] = fmaf(f0, f0, fmaf(f1, f1, sk[pj][r >> 1]));
                }
#pragma unroll
            for (int mi = 0; mi < 3; mi++)
#pragma unroll
                for (int pj = 0; pj < 3; pj++) {
                    mma16816(c[mi][2 * pj],     ah[mi], &bh[pj][0]);
                    mma16816(c[mi][2 * pj + 1], ah[mi], &bh[pj][2]);
                }
#pragma unroll
            for (int mi = 0; mi < 3; mi++)
#pragma unroll
                for (int pj = 0; pj < 3; pj++) {
                    mma16816(c[mi][2 * pj],     ah[mi], &bl[pj][0]);
                    mma16816(c[mi][2 * pj + 1], ah[mi], &bl[pj][2]);
                }
#pragma unroll
            for (int mi = 0; mi < 3; mi++)
#pragma unroll
                for (int pj = 0; pj < 3; pj++) {
                    mma16816(c[mi][2 * pj],     al[mi], &bh[pj][0]);
                    mma16816(c[mi][2 * pj + 1], al[mi], &bh[pj][2]);
                }
        }
        __syncthreads();
    }

    float* attn_s = (float*)qsm;
    float* ssq_qs = attn_s + 2304;
    float* ssq_ks = ssq_qs + 48;
    for (int i = t; i < 2400; i += 256) attn_s[i] = 0.f;
    __syncthreads();

#pragma unroll
    for (int mi = 0; mi < 3; mi++)
#pragma unroll
        for (int nj = 0; nj < 6; nj++) {
            int row = mi * 16 + grp, col = nj * 8 + tig * 2;
            atomicAdd(&attn_s[row * 48 + col],           c[mi][nj][0]);
            atomicAdd(&attn_s[row * 48 + col + 1],       c[mi][nj][1]);
            atomicAdd(&attn_s[(row + 8) * 48 + col],     c[mi][nj][2]);
            atomicAdd(&attn_s[(row + 8) * 48 + col + 1], c[mi][nj][3]);
        }
#pragma unroll
    for (int mi = 0; mi < 3; mi++)
#pragma unroll
        for (int h = 0; h < 2; h++) {
            float v = sq[mi][h];
            v += __shfl_xor_sync(~0u, v, 1);
            v += __shfl_xor_sync(~0u, v, 2);
            if (tig == 0) atomicAdd(&ssq_qs[mi * 16 + h * 8 + grp], v);
            float u = sk[mi][h];
            u += __shfl_xor_sync(~0u, u, 1);
            u += __shfl_xor_sync(~0u, u, 2);
            if (tig == 0) atomicAdd(&ssq_ks[mi * 16 + h * 8 + grp], u);
        }
    __syncthreads();

    for (int i = t; i < 2304; i += 256) atomicAdd(&g_attn[bn * 2304 + i], attn_s[i]);
    if (t < 48) atomicAdd(&g_ssq_q[bn * 48 + t], ssq_qs[t]);
    else if (t < 96) atomicAdd(&g_ssq_k[bn * 48 + t - 48], ssq_ks[t - 48]);
}

// ---------------- softmax with l2-norm scaling + temperature ----------------
__global__ void softmax48_kernel(const float* __restrict__ temp)
{
    int row = blockIdx.x;
    int bn = row / CH;
    int n = bn & (HEADS - 1);
    int l = threadIdx.x;
    float tf = temp[n];
    float iq = rsqrtf(fmaxf(g_ssq_q[row], 1e-12f));
    float* arow = g_attn + (size_t)row * CH;

    float ik0 = rsqrtf(fmaxf(g_ssq_k[bn * CH + l], 1e-12f));
    float v0 = arow[l] * iq * ik0 * tf;
    float v1 = -3.0e38f;
    if (l < 16) {
        float ik1 = rsqrtf(fmaxf(g_ssq_k[bn * CH + l + 32], 1e-12f));
        v1 = arow[l + 32] * iq * ik1 * tf;
    }
    float m = fmaxf(v0, v1);
#pragma unroll
    for (int o = 16; o > 0; o >>= 1) m = fmaxf(m, __shfl_xor_sync(~0u, m, o));
    float e0 = expf(v0 - m);
    float e1 = (l < 16) ? expf(v1 - m) : 0.f;
    float s = e0 + e1;
#pragma unroll
    for (int o = 16; o > 0; o >>= 1) s += __shfl_xor_sync(~0u, s, o);
    float inv = 1.f / s;
    arow[l] = e0 * inv;
    if (l < 16) arow[l + 32] = e1 * inv;
}

// ---------------- out = attn @ V (fp16 V in, fp16 O out) ----------------
__global__ __launch_bounds__(256) void av_kernel()
{
    int bn = blockIdx.x;
    int s2 = blockIdx.y * 256 + threadIdx.x;

    __shared__ float As[CH * CH];
    for (int f = threadIdx.x; f < CH * CH; f += 256) As[f] = g_attn[bn * CH * CH + f];
    __syncthreads();

    const __half2* vb = (const __half2*)(g_v_h + (size_t)bn * CH * HW) + s2;
    float2 vr[CH];
#pragma unroll
    for (int e = 0; e < CH; e++) vr[e] = __half22float2(vb[(size_t)e * (HW / 2)]);

    __half2* ob = (__half2*)(g_o_h + (size_t)bn * CH * HW) + s2;
    for (int d = 0; d < CH; d++) {
        float2 a = make_float2(0.f, 0.f);
#pragma unroll
        for (int e = 0; e < CH; e++) {
            float w = As[d * CH + e];
            a.x = fmaf(w, vr[e].x, a.x);
            a.y = fmaf(w, vr[e].y, a.y);
        }
        ob[(size_t)d * (HW / 2)] = __floats2half2_rn(a.x, a.y);
    }
}

// ---------------- launch ----------------
extern "C" void kernel_launch(void* const* d_in, const int* in_sizes, int n_in,
                              void* d_out, int out_size)
{
    const float* x      = (const float*)d_in[0];
    const float* qkv_w  = (const float*)d_in[1];
    const float* dw_w   = (const float*)d_in[2];
    const float* proj_w = (const float*)d_in[3];
    const float* temp   = (const float*)d_in[4];
    float* out = (float*)d_out;

    __half *qkv_buf, *o_buf;
    cudaGetSymbolAddress((void**)&qkv_buf, g_qkv_h);
    cudaGetSymbolAddress((void**)&o_buf, g_o_h);
    __half *wqh, *wql, *wph, *wpl;
    cudaGetSymbolAddress((void**)&wqh, g_wqkv_h);
    cudaGetSymbolAddress((void**)&wql, g_wqkv_l);
    cudaGetSymbolAddress((void**)&wph, g_wproj_h);
    cudaGetSymbolAddress((void**)&wpl, g_wproj_l);

    cudaFuncSetAttribute(gemm_fp16_split<false, true>, cudaFuncAttributeMaxDynamicSharedMemorySize, GEMM_SMEM);
    cudaFuncSetAttribute(gemm_fp16_split<true, false>, cudaFuncAttributeMaxDynamicSharedMemorySize, GEMM_SMEM);
    cudaFuncSetAttribute(qk_mma_kernel, cudaFuncAttributeMaxDynamicSharedMemorySize, QK_SMEM);

    const int M = NB * HW;

    // launches 1-3: prep (slot 4 = qkv GEMM gets profiled)
    wprep_qkvw_kernel<<<(C3 * KDIM + 255) / 256, 256>>>(qkv_w);
    wprep_projw_kernel<<<(NC * KDIM + 255) / 256, 256>>>(proj_w);
    zero_kernel<<<(BNT * CH * CH + 255) / 256, 256>>>();

    // 4) qkv = x @ qkv_w  (fp32 in, fp16 out)   <-- profiled slot
    gemm_fp16_split<false, true><<<M / 128, 256, GEMM_SMEM>>>(x, wqh, wql, qkv_buf, C3);

    // 5) depthwise 3x3 + split (fp16 in; q/k bf16 hi/lo, v fp16)
    dwconv_split_kernel<<<(NB * HW * (C3 / 4)) / 256, 256>>>(dw_w);

    // 6) QK^T (tensor cores) + fused square sums
    qk_mma_kernel<<<dim3(BNT, 8), 256, QK_SMEM>>>();

    // 7) scale + softmax
    softmax48_kernel<<<BNT * CH, 32>>>(temp);

    // 8) out = attn @ V (fp16 -> fp16)
    av_kernel<<<dim3(BNT, HW / 512), 256>>>();

    // 9) projection (fp16 in, fp32 out)
    gemm_fp16_split<true, false><<<M / 128, 256, GEMM_SMEM>>>(o_buf, wph, wpl, out, NC);
}

// round 13
// speedup vs baseline: 1.0817x; 1.0003x over previous
#include <cuda_runtime.h>
#include <cuda_bf16.h>
#include <cuda_fp16.h>
#include <math.h>
#include <stdint.h>

#define NB 8
#define HH 128
#define WW 128
#define NC 192
#define C3 576
#define HEADS 4
#define CH 48
#define HW 16384
#define BNT 32
#define KDIM 192

// ---------------- scratch ----------------
__device__ __half g_qkv_h[(size_t)NB * HW * C3];      // qkv intermediate, fp16
__device__ __nv_bfloat16 g_qh[(size_t)NB * HW * NC];
__device__ __nv_bfloat16 g_ql[(size_t)NB * HW * NC];
__device__ __nv_bfloat16 g_kh[(size_t)NB * HW * NC];
__device__ __nv_bfloat16 g_kl[(size_t)NB * HW * NC];
__device__ __half g_v_h[(size_t)NB * HW * NC];        // v, fp16
__device__ __half g_o_h[(size_t)NB * HW * NC];        // attn@V output, fp16
__device__ float g_attn[BNT * CH * CH];
__device__ float g_ssq_q[BNT * CH];
__device__ float g_ssq_k[BNT * CH];
// GEMM weights: fp16 hi/lo, [N][K]
__device__ __half g_wqkv_h[C3 * KDIM];
__device__ __half g_wqkv_l[C3 * KDIM];
__device__ __half g_wproj_h[NC * KDIM];
__device__ __half g_wproj_l[NC * KDIM];

// ---------------- helpers ----------------
__device__ __forceinline__ uint32_t smem_u32(const void* p) {
    uint32_t a;
    asm("{ .reg .u64 t; cvta.to.shared.u64 t, %1; cvt.u32.u64 %0, t; }" : "=r"(a) : "l"(p));
    return a;
}
__device__ __forceinline__ uint32_t pk_hi(float a, float b) {   // bf16 pack (q/k path)
    __nv_bfloat16 ha = __float2bfloat16(a), hb = __float2bfloat16(b);
    uint16_t ra = *(uint16_t*)&ha, rb = *(uint16_t*)&hb;
    return (uint32_t)ra | ((uint32_t)rb << 16);
}
__device__ __forceinline__ uint32_t pk_lo(float a, float b) {
    __nv_bfloat16 ha = __float2bfloat16(a), hb = __float2bfloat16(b);
    float la = a - __bfloat162float(ha), lb = b - __bfloat162float(hb);
    __nv_bfloat16 xa = __float2bfloat16(la), xb = __float2bfloat16(lb);
    uint16_t ra = *(uint16_t*)&xa, rb = *(uint16_t*)&xb;
    return (uint32_t)ra | ((uint32_t)rb << 16);
}
__device__ __forceinline__ uint32_t pkh(float a, float b) {     // fp16x2 pack
    __half2 h = __floats2half2_rn(a, b);
    return *(uint32_t*)&h;
}
__device__ __forceinline__ float bf_lo(uint32_t v) { return __uint_as_float(v << 16); }
__device__ __forceinline__ float bf_hi(uint32_t v) { return __uint_as_float(v & 0xffff0000u); }

__device__ __forceinline__ void mma16816(float* c, const uint32_t* a, const uint32_t* b) {
    asm volatile(
        "mma.sync.aligned.m16n8k16.row.col.f32.bf16.bf16.f32 "
        "{%0,%1,%2,%3}, {%4,%5,%6,%7}, {%8,%9}, {%0,%1,%2,%3};\n"
        : "+f"(c[0]), "+f"(c[1]), "+f"(c[2]), "+f"(c[3])
        : "r"(a[0]), "r"(a[1]), "r"(a[2]), "r"(a[3]), "r"(b[0]), "r"(b[1]));
}
__device__ __forceinline__ void mma16816h(float* c, const uint32_t* a, const uint32_t* b) {
    asm volatile(
        "mma.sync.aligned.m16n8k16.row.col.f32.f16.f16.f32 "
        "{%0,%1,%2,%3}, {%4,%5,%6,%7}, {%8,%9}, {%0,%1,%2,%3};\n"
        : "+f"(c[0]), "+f"(c[1]), "+f"(c[2]), "+f"(c[3])
        : "r"(a[0]), "r"(a[1]), "r"(a[2]), "r"(a[3]), "r"(b[0]), "r"(b[1]));
}
__device__ __forceinline__ void ldmx4(uint32_t* r, uint32_t addr) {
    asm volatile("ldmatrix.sync.aligned.m8n8.x4.shared.b16 {%0,%1,%2,%3}, [%4];"
        : "=r"(r[0]), "=r"(r[1]), "=r"(r[2]), "=r"(r[3]) : "r"(addr));
}
#define CP_ASYNC16(dst, src) asm volatile("cp.async.ca.shared.global [%0], [%1], 16;" :: "r"(dst), "l"(src))
#define CP_COMMIT()          asm volatile("cp.async.commit_group;" ::: "memory")
#define CP_WAIT(n)           asm volatile("cp.async.wait_group %0;" :: "n"(n) : "memory")

// ---------------- weight prep (3 launches so slot 4 = qkv GEMM in ncu) ----------------
__global__ void wprep_qkvw_kernel(const float* __restrict__ qkvw)
{
    int i = blockIdx.x * 256 + threadIdx.x;
    if (i < C3 * KDIM) {
        int n = i / KDIM, k = i % KDIM;
        float v = qkvw[(size_t)k * C3 + n];
        __half h = __float2half_rn(v);
        g_wqkv_h[i] = h;
        g_wqkv_l[i] = __float2half_rn(v - __half2float(h));
    }
}
__global__ void wprep_projw_kernel(const float* __restrict__ projw)
{
    int i = blockIdx.x * 256 + threadIdx.x;
    if (i < NC * KDIM) {
        int n = i / KDIM, k = i % KDIM;
        float v = projw[(size_t)k * NC + n];
        __half h = __float2half_rn(v);
        g_wproj_h[i] = h;
        g_wproj_l[i] = __float2half_rn(v - __half2float(h));
    }
}
__global__ void zero_kernel()
{
    int i = blockIdx.x * 256 + threadIdx.x;
    if (i < BNT * CH * CH) g_attn[i] = 0.f;
    if (i < BNT * CH) { g_ssq_q[i] = 0.f; g_ssq_k[i] = 0.f; }
}

// ---------------- fp16 2-term GEMM (templated A input / output type) ----------------
// D = A16*Bh + A16*Bl. CTA tile 128x64, 256 thr, 8 warps (4M x 2N), warp tile 32x32.
// smem 102400 -> 2 CTAs/SM.
// AHALF: A already fp16 in gmem (pure cp.async); else fp32 with convert.
// OUTHALF: store __half output; else fp32.
#define ASTRIDE 200
#define ROWB    (ASTRIDE * 2)          // 400 bytes per row
#define OFF_A   0                       // 128 * 400 = 51200
#define OFF_BH  (128 * ROWB)            // 51200
#define OFF_BL  (128 * ROWB + 64 * ROWB)// 76800
#define GEMM_SMEM (128 * ROWB + 2 * 64 * ROWB)   // 102400

template<bool AHALF, bool OUTHALF>
__global__ __launch_bounds__(256, 2) void gemm_fp16_split(
    const void* __restrict__ Aptr, const __half* __restrict__ Wh,
    const __half* __restrict__ Wl, void* __restrict__ Coutp, int Ntot)
{
    extern __shared__ char smem[];
    const uint32_t sbase = smem_u32(smem);
    const uint32_t sA  = sbase + OFF_A;
    const uint32_t sBh = sbase + OFF_BH;
    const uint32_t sBl = sbase + OFF_BL;

    const int t = threadIdx.x;
    const int warp = t >> 5, lane = t & 31;
    const int grp = lane >> 2, tig = lane & 3;
    const int warpM = warp >> 1, warpN = warp & 1;      // 4 x 2
    const size_t m0 = (size_t)blockIdx.x * 128;
    const int nChunks = Ntot >> 6;

    const uint32_t aOff = (uint32_t)(warpM * 32 + (lane & 15)) * ROWB + ((lane >> 4) * 16);
    const uint32_t bOff = (uint32_t)(warpN * 32 + ((lane >> 4) * 8) + (lane & 7)) * ROWB
                          + (((lane >> 3) & 1) * 16);

    // ---- issue B chunk 0 load ----
    {
        const uint4* bh = (const uint4*)Wh;
        const uint4* bl = (const uint4*)Wl;
#pragma unroll
        for (int i = t; i < 1536; i += 256) {          // 64 rows * 24 uint4
            int row = i / 24, cb = (i % 24) * 16;
            uint32_t o = (uint32_t)row * ROWB + cb;
            CP_ASYNC16(sBh + o, bh + i);
            CP_ASYNC16(sBl + o, bl + i);
        }
        CP_COMMIT();
    }
    // ---- A tile ----
    if (AHALF) {
        // fp16 rows: pure async copy, 128 rows * 24 uint4
        const __half* Ah = (const __half*)Aptr;
#pragma unroll
        for (int i = t; i < 3072; i += 256) {
            int row = i / 24, seg = i % 24;
            const uint4* src = (const uint4*)(Ah + (m0 + row) * KDIM) + seg;
            CP_ASYNC16(sA + (uint32_t)row * ROWB + seg * 16, src);
        }
        CP_COMMIT();
    } else {
        const float* Af = (const float*)Aptr;
        int row = t >> 1, half = t & 1;
        const float4* ar = (const float4*)(Af + (m0 + row) * KDIM + half * 96);
        __half* ap = (__half*)(smem + OFF_A) + row * ASTRIDE + half * 96;
#pragma unroll
        for (int j = 0; j < 24; j++) {
            float4 v = ar[j];
            *(uint32_t*)(ap + j * 4)     = pkh(v.x, v.y);
            *(uint32_t*)(ap + j * 4 + 2) = pkh(v.z, v.w);
        }
    }
    CP_WAIT(0);
    __syncthreads();

    float c[2][4][4];

    for (int nc = 0; nc < nChunks; nc++) {
#pragma unroll
        for (int mi = 0; mi < 2; mi++)
#pragma unroll
            for (int nj = 0; nj < 4; nj++)
#pragma unroll
                for (int j = 0; j < 4; j++) c[mi][nj][j] = 0.f;

#pragma unroll
        for (int ks = 0; ks < 12; ks++) {
            const uint32_t k32 = ks * 32;
            uint32_t a0[4], a1[4], bh0[4], bh1[4], bl0[4], bl1[4];
            ldmx4(a0, sA + aOff + k32);
            ldmx4(a1, sA + aOff + 16 * ROWB + k32);
            ldmx4(bh0, sBh + bOff + k32);
            ldmx4(bh1, sBh + bOff + 16 * ROWB + k32);
            ldmx4(bl0, sBl + bOff + k32);
            ldmx4(bl1, sBl + bOff + 16 * ROWB + k32);
            // sweep 1: A * Bh (accumulator reuse distance 8)
            mma16816h(c[0][0], a0, &bh0[0]);
            mma16816h(c[0][1], a0, &bh0[2]);
            mma16816h(c[0][2], a0, &bh1[0]);
            mma16816h(c[0][3], a0, &bh1[2]);
            mma16816h(c[1][0], a1, &bh0[0]);
            mma16816h(c[1][1], a1, &bh0[2]);
            mma16816h(c[1][2], a1, &bh1[0]);
            mma16816h(c[1][3], a1, &bh1[2]);
            // sweep 2: A * Bl
            mma16816h(c[0][0], a0, &bl0[0]);
            mma16816h(c[0][1], a0, &bl0[2]);
            mma16816h(c[0][2], a0, &bl1[0]);
            mma16816h(c[0][3], a0, &bl1[2]);
            mma16816h(c[1][0], a1, &bl0[0]);
            mma16816h(c[1][1], a1, &bl0[2]);
            mma16816h(c[1][2], a1, &bl1[0]);
            mma16816h(c[1][3], a1, &bl1[2]);
        }
        __syncthreads();   // all warps done reading this B chunk

        // issue next B chunk load (overlaps epilogue stores; partner CTA hides rest)
        if (nc + 1 < nChunks) {
            const uint4* bh = (const uint4*)(Wh + (size_t)(nc + 1) * 64 * KDIM);
            const uint4* bl = (const uint4*)(Wl + (size_t)(nc + 1) * 64 * KDIM);
#pragma unroll
            for (int i = t; i < 1536; i += 256) {
                int row = i / 24, cb = (i % 24) * 16;
                uint32_t o = (uint32_t)row * ROWB + cb;
                CP_ASYNC16(sBh + o, bh + i);
                CP_ASYNC16(sBl + o, bl + i);
            }
            CP_COMMIT();
        }

        // epilogue: store 128x64 chunk
        const int n0 = nc * 64;
#pragma unroll
        for (int mi = 0; mi < 2; mi++) {
            size_t row = m0 + warpM * 32 + mi * 16 + grp;
#pragma unroll
            for (int nj = 0; nj < 4; nj++) {
                int col = n0 + warpN * 32 + nj * 8 + tig * 2;
                if (OUTHALF) {
                    __half* co = (__half*)Coutp;
                    *(uint32_t*)(co + row * Ntot + col)       = pkh(c[mi][nj][0], c[mi][nj][1]);
                    *(uint32_t*)(co + (row + 8) * Ntot + col) = pkh(c[mi][nj][2], c[mi][nj][3]);
                } else {
                    float* co = (float*)Coutp;
                    *(float2*)(co + row * Ntot + col) = make_float2(c[mi][nj][0], c[mi][nj][1]);
                    *(float2*)(co + (row + 8) * Ntot + col) = make_float2(c[mi][nj][2], c[mi][nj][3]);
                }
            }
        }
        CP_WAIT(0);
        __syncthreads();
    }
}

// ---------------- depthwise 3x3 SAME + split (fp16 input; q/k -> bf16 hi/lo, v -> fp16) ----------------
__global__ __launch_bounds__(256) void dwconv_split_kernel(const float* __restrict__ w)
{
    int gid = blockIdx.x * 256 + threadIdx.x;
    int c4 = gid % 144;
    int p = gid / 144;
    int x = p % WW;
    int y = (p / WW) % HH;
    int b = p / HW;
    int c = c4 * 4;

    float4 acc = make_float4(0.f, 0.f, 0.f, 0.f);
#pragma unroll
    for (int dy = -1; dy <= 1; dy++) {
        int yy = y + dy;
        if (yy < 0 || yy >= HH) continue;
#pragma unroll
        for (int dx = -1; dx <= 1; dx++) {
            int xx = x + dx;
            if (xx < 0 || xx >= WW) continue;
            const __half2* iv2 = (const __half2*)(g_qkv_h + ((size_t)((b * HH + yy) * WW + xx)) * C3 + c);
            float2 p0 = __half22float2(iv2[0]);
            float2 p1 = __half22float2(iv2[1]);
            const float4 wv = *(const float4*)(w + (size_t)((dy + 1) * 3 + (dx + 1)) * C3 + c);
            acc.x = fmaf(p0.x, wv.x, acc.x);
            acc.y = fmaf(p0.y, wv.y, acc.y);
            acc.z = fmaf(p1.x, wv.z, acc.z);
            acc.w = fmaf(p1.y, wv.w, acc.w);
        }
    }
    if (c < NC) {
        int cc = c;
        *(uint2*)&g_qh[(size_t)p * NC + cc] = make_uint2(pk_hi(acc.x, acc.y), pk_hi(acc.z, acc.w));
        *(uint2*)&g_ql[(size_t)p * NC + cc] = make_uint2(pk_lo(acc.x, acc.y), pk_lo(acc.z, acc.w));
    } else if (c < 2 * NC) {
        int cc = c - NC;
        *(uint2*)&g_kh[(size_t)p * NC + cc] = make_uint2(pk_hi(acc.x, acc.y), pk_hi(acc.z, acc.w));
        *(uint2*)&g_kl[(size_t)p * NC + cc] = make_uint2(pk_lo(acc.x, acc.y), pk_lo(acc.z, acc.w));
    } else {
        int cc = c - 2 * NC;
        *(uint2*)&g_v_h[(size_t)p * NC + cc] = make_uint2(pkh(acc.x, acc.y), pkh(acc.z, acc.w));
    }
}

// ---------------- QK^T via mma.sync bf16-split + fused ssq ----------------
#define QK_PLANE 25344                     // 48 rows * 528 bytes
#define QK_SMEM  (4 * QK_PLANE)            // 101376

__global__ __launch_bounds__(256) void qk_mma_kernel()
{
    extern __shared__ char qsm[];
    const uint32_t sb = smem_u32(qsm);
    const int t = threadIdx.x, lane = t & 31, warp = t >> 5;
    const int grp = lane >> 2, tig = lane & 3;
    const int bn = blockIdx.x;
    const int sbase0 = blockIdx.y * 2048;

    const uint32_t aAddr = sb + (uint32_t)(lane & 15) * 528 + warp * 64 + ((lane >> 4) * 16);
    const uint32_t bAddr = sb + (uint32_t)(((lane >> 4) * 8) + (lane & 7)) * 528 + warp * 64
                           + (((lane >> 3) & 1) * 16);

    float c[3][6][4];
#pragma unroll
    for (int mi = 0; mi < 3; mi++)
#pragma unroll
        for (int nj = 0; nj < 6; nj++)
#pragma unroll
            for (int j = 0; j < 4; j++) c[mi][nj][j] = 0.f;
    float sq[3][2] = {{0.f,0.f},{0.f,0.f},{0.f,0.f}};
    float sk[3][2] = {{0.f,0.f},{0.f,0.f},{0.f,0.f}};

    for (int stage = 0; stage < 8; stage++) {
        const int sbase = sbase0 + stage * 256;
        const __nv_bfloat16* gp0 = g_qh; const __nv_bfloat16* gp1 = g_ql;
        const __nv_bfloat16* gp2 = g_kh; const __nv_bfloat16* gp3 = g_kl;
#pragma unroll
        for (int pl = 0; pl < 4; pl++) {
            const __nv_bfloat16* gp = (pl == 0) ? gp0 : (pl == 1) ? gp1 : (pl == 2) ? gp2 : gp3;
            uint32_t sp = sb + pl * QK_PLANE;
            for (int i = t; i < 1536; i += 256) {
                int r = i >> 5, seg = i & 31;
                const void* src = gp + (((size_t)(bn * 48 + r)) << 14) + sbase + seg * 8;
                CP_ASYNC16(sp + (uint32_t)r * 528 + seg * 16, src);
            }
        }
        CP_COMMIT();
        CP_WAIT(0);
        __syncthreads();

#pragma unroll
        for (int ks = 0; ks < 2; ks++) {
            const uint32_t kb = ks * 32;
            uint32_t ah[3][4], al[3][4], bh[3][4], bl[3][4];
#pragma unroll
            for (int mi = 0; mi < 3; mi++) {
                ldmx4(ah[mi], aAddr + (uint32_t)(mi * 16) * 528 + kb);
                ldmx4(al[mi], aAddr + QK_PLANE + (uint32_t)(mi * 16) * 528 + kb);
            }
#pragma unroll
            for (int pj = 0; pj < 3; pj++) {
                ldmx4(bh[pj], bAddr + 2 * QK_PLANE + (uint32_t)(pj * 16) * 528 + kb);
                ldmx4(bl[pj], bAddr + 3 * QK_PLANE + (uint32_t)(pj * 16) * 528 + kb);
            }
#pragma unroll
            for (int mi = 0; mi < 3; mi++)
#pragma unroll
                for (int r = 0; r < 4; r++) {
                    float f0 = bf_lo(ah[mi][r]) + bf_lo(al[mi][r]);
                    float f1 = bf_hi(ah[mi][r]) + bf_hi(al[mi][r]);
                    sq[mi][r & 1] = fmaf(f0, f0, fmaf(f1, f1, sq[mi][r & 1]));
                }
#pragma unroll
            for (int pj = 0; pj < 3; pj++)
#pragma unroll
                for (int r = 0; r < 4; r++) {
                    float f0 = bf_lo(bh[pj][r]) + bf_lo(bl[pj][r]);
                    float f1 = bf_hi(bh[pj][r]) + bf_hi(bl[pj][r]);
                    sk[pj][r >> 1] = fmaf(f0, f0, fmaf(f1, f1, sk[pj][r >> 1]));
                }
#pragma unroll
            for (int mi = 0; mi < 3; mi++)
#pragma unroll
                for (int pj = 0; pj < 3; pj++) {
                    mma16816(c[mi][2 * pj],     ah[mi], &bh[pj][0]);
                    mma16816(c[mi][2 * pj + 1], ah[mi], &bh[pj][2]);
                }
#pragma unroll
            for (int mi = 0; mi < 3; mi++)
#pragma unroll
                for (int pj = 0; pj < 3; pj++) {
                    mma16816(c[mi][2 * pj],     ah[mi], &bl[pj][0]);
                    mma16816(c[mi][2 * pj + 1], ah[mi], &bl[pj][2]);
                }
#pragma unroll
            for (int mi = 0; mi < 3; mi++)
#pragma unroll
                for (int pj = 0; pj < 3; pj++) {
                    mma16816(c[mi][2 * pj],     al[mi], &bh[pj][0]);
                    mma16816(c[mi][2 * pj + 1], al[mi], &bh[pj][2]);
                }
        }
        __syncthreads();
    }

    float* attn_s = (float*)qsm;
    float* ssq_qs = attn_s + 2304;
    float* ssq_ks = ssq_qs + 48;
    for (int i = t; i < 2400; i += 256) attn_s[i] = 0.f;
    __syncthreads();

#pragma unroll
    for (int mi = 0; mi < 3; mi++)
#pragma unroll
        for (int nj = 0; nj < 6; nj++) {
            int row = mi * 16 + grp, col = nj * 8 + tig * 2;
            atomicAdd(&attn_s[row * 48 + col],           c[mi][nj][0]);
            atomicAdd(&attn_s[row * 48 + col + 1],       c[mi][nj][1]);
            atomicAdd(&attn_s[(row + 8) * 48 + col],     c[mi][nj][2]);
            atomicAdd(&attn_s[(row + 8) * 48 + col + 1], c[mi][nj][3]);
        }
#pragma unroll
    for (int mi = 0; mi < 3; mi++)
#pragma unroll
        for (int h = 0; h < 2; h++) {
            float v = sq[mi][h];
            v += __shfl_xor_sync(~0u, v, 1);
            v += __shfl_xor_sync(~0u, v, 2);
            if (tig == 0) atomicAdd(&ssq_qs[mi * 16 + h * 8 + grp], v);
            float u = sk[mi][h];
            u += __shfl_xor_sync(~0u, u, 1);
            u += __shfl_xor_sync(~0u, u, 2);
            if (tig == 0) atomicAdd(&ssq_ks[mi * 16 + h * 8 + grp], u);
        }
    __syncthreads();

    for (int i = t; i < 2304; i += 256) atomicAdd(&g_attn[bn * 2304 + i], attn_s[i]);
    if (t < 48) atomicAdd(&g_ssq_q[bn * 48 + t], ssq_qs[t]);
    else if (t < 96) atomicAdd(&g_ssq_k[bn * 48 + t - 48], ssq_ks[t - 48]);
}

// ---------------- softmax with l2-norm scaling + temperature ----------------
__global__ void softmax48_kernel(const float* __restrict__ temp)
{
    int row = blockIdx.x;
    int bn = row / CH;
    int n = bn & (HEADS - 1);
    int l = threadIdx.x;
    float tf = temp[n];
    float iq = rsqrtf(fmaxf(g_ssq_q[row], 1e-12f));
    float* arow = g_attn + (size_t)row * CH;

    float ik0 = rsqrtf(fmaxf(g_ssq_k[bn * CH + l], 1e-12f));
    float v0 = arow[l] * iq * ik0 * tf;
    float v1 = -3.0e38f;
    if (l < 16) {
        float ik1 = rsqrtf(fmaxf(g_ssq_k[bn * CH + l + 32], 1e-12f));
        v1 = arow[l + 32] * iq * ik1 * tf;
    }
    float m = fmaxf(v0, v1);
#pragma unroll
    for (int o = 16; o > 0; o >>= 1) m = fmaxf(m, __shfl_xor_sync(~0u, m, o));
    float e0 = expf(v0 - m);
    float e1 = (l < 16) ? expf(v1 - m) : 0.f;
    float s = e0 + e1;
#pragma unroll
    for (int o = 16; o > 0; o >>= 1) s += __shfl_xor_sync(~0u, s, o);
    float inv = 1.f / s;
    arow[l] = e0 * inv;
    if (l < 16) arow[l + 32] = e1 * inv;
}

// ---------------- out = attn @ V (fp16 V in, fp16 O out) ----------------
__global__ __launch_bounds__(256) void av_kernel()
{
    int bn = blockIdx.x;
    int s2 = blockIdx.y * 256 + threadIdx.x;

    __shared__ float As[CH * CH];
    for (int f = threadIdx.x; f < CH * CH; f += 256) As[f] = g_attn[bn * CH * CH + f];
    __syncthreads();

    const __half2* vb = (const __half2*)(g_v_h + (size_t)bn * CH * HW) + s2;
    float2 vr[CH];
#pragma unroll
    for (int e = 0; e < CH; e++) vr[e] = __half22float2(vb[(size_t)e * (HW / 2)]);

    __half2* ob = (__half2*)(g_o_h + (size_t)bn * CH * HW) + s2;
    for (int d = 0; d < CH; d++) {
        float2 a = make_float2(0.f, 0.f);
#pragma unroll
        for (int e = 0; e < CH; e++) {
            float w = As[d * CH + e];
            a.x = fmaf(w, vr[e].x, a.x);
            a.y = fmaf(w, vr[e].y, a.y);
        }
        ob[(size_t)d * (HW / 2)] = __floats2half2_rn(a.x, a.y);
    }
}

// ---------------- launch ----------------
extern "C" void kernel_launch(void* const* d_in, const int* in_sizes, int n_in,
                              void* d_out, int out_size)
{
    const float* x      = (const float*)d_in[0];
    const float* qkv_w  = (const float*)d_in[1];
    const float* dw_w   = (const float*)d_in[2];
    const float* proj_w = (const float*)d_in[3];
    const float* temp   = (const float*)d_in[4];
    float* out = (float*)d_out;

    __half *qkv_buf, *o_buf;
    cudaGetSymbolAddress((void**)&qkv_buf, g_qkv_h);
    cudaGetSymbolAddress((void**)&o_buf, g_o_h);
    __half *wqh, *wql, *wph, *wpl;
    cudaGetSymbolAddress((void**)&wqh, g_wqkv_h);
    cudaGetSymbolAddress((void**)&wql, g_wqkv_l);
    cudaGetSymbolAddress((void**)&wph, g_wproj_h);
    cudaGetSymbolAddress((void**)&wpl, g_wproj_l);

    cudaFuncSetAttribute(gemm_fp16_split<false, true>, cudaFuncAttributeMaxDynamicSharedMemorySize, GEMM_SMEM);
    cudaFuncSetAttribute(gemm_fp16_split<true, false>, cudaFuncAttributeMaxDynamicSharedMemorySize, GEMM_SMEM);
    cudaFuncSetAttribute(qk_mma_kernel, cudaFuncAttributeMaxDynamicSharedMemorySize, QK_SMEM);

    const int M = NB * HW;

    // launches 1-3: prep (slot 4 = qkv GEMM gets profiled)
    wprep_qkvw_kernel<<<(C3 * KDIM + 255) / 256, 256>>>(qkv_w);
    wprep_projw_kernel<<<(NC * KDIM + 255) / 256, 256>>>(proj_w);
    zero_kernel<<<(BNT * CH * CH + 255) / 256, 256>>>();

    // 4) qkv = x @ qkv_w  (fp32 in, fp16 out)   <-- profiled slot
    gemm_fp16_split<false, true><<<M / 128, 256, GEMM_SMEM>>>(x, wqh, wql, qkv_buf, C3);

    // 5) depthwise 3x3 + split (fp16 in; q/k bf16 hi/lo, v fp16)
    dwconv_split_kernel<<<(NB * HW * (C3 / 4)) / 256, 256>>>(dw_w);

    // 6) QK^T (tensor cores) + fused square sums
    qk_mma_kernel<<<dim3(BNT, 8), 256, QK_SMEM>>>();

    // 7) scale + softmax
    softmax48_kernel<<<BNT * CH, 32>>>(temp);

    // 8) out = attn @ V (fp16 -> fp16)
    av_kernel<<<dim3(BNT, HW / 512), 256>>>();

    // 9) projection (fp16 in, fp32 out)
    gemm_fp16_split<true, false><<<M / 128, 256, GEMM_SMEM>>>(o_buf, wph, wpl, out, NC);
}

// round 14
// speedup vs baseline: 1.0826x; 1.0008x over previous
#include <cuda_runtime.h>
#include <cuda_bf16.h>
#include <cuda_fp16.h>
#include <math.h>
#include <stdint.h>

#define NB 8
#define HH 128
#define WW 128
#define NC 192
#define C3 576
#define HEADS 4
#define CH 48
#define HW 16384
#define BNT 32
#define KDIM 192

// ---------------- scratch ----------------
__device__ __half g_qkv_h[(size_t)NB * HW * C3];      // qkv intermediate, fp16
__device__ __nv_bfloat16 g_qh[(size_t)NB * HW * NC];
__device__ __nv_bfloat16 g_ql[(size_t)NB * HW * NC];
__device__ __nv_bfloat16 g_kh[(size_t)NB * HW * NC];
__device__ __nv_bfloat16 g_kl[(size_t)NB * HW * NC];
__device__ __half g_v_h[(size_t)NB * HW * NC];        // v, fp16
__device__ __half g_o_h[(size_t)NB * HW * NC];        // attn@V output, fp16
__device__ float g_attn[BNT * CH * CH];
__device__ float g_ssq_q[BNT * CH];
__device__ float g_ssq_k[BNT * CH];
// GEMM weights: fp16 hi/lo, [N][K]
__device__ __half g_wqkv_h[C3 * KDIM];
__device__ __half g_wqkv_l[C3 * KDIM];
__device__ __half g_wproj_h[NC * KDIM];
__device__ __half g_wproj_l[NC * KDIM];

// ---------------- helpers ----------------
__device__ __forceinline__ uint32_t smem_u32(const void* p) {
    uint32_t a;
    asm("{ .reg .u64 t; cvta.to.shared.u64 t, %1; cvt.u32.u64 %0, t; }" : "=r"(a) : "l"(p));
    return a;
}
__device__ __forceinline__ uint32_t pk_hi(float a, float b) {   // bf16 pack (q/k path)
    __nv_bfloat16 ha = __float2bfloat16(a), hb = __float2bfloat16(b);
    uint16_t ra = *(uint16_t*)&ha, rb = *(uint16_t*)&hb;
    return (uint32_t)ra | ((uint32_t)rb << 16);
}
__device__ __forceinline__ uint32_t pk_lo(float a, float b) {
    __nv_bfloat16 ha = __float2bfloat16(a), hb = __float2bfloat16(b);
    float la = a - __bfloat162float(ha), lb = b - __bfloat162float(hb);
    __nv_bfloat16 xa = __float2bfloat16(la), xb = __float2bfloat16(lb);
    uint16_t ra = *(uint16_t*)&xa, rb = *(uint16_t*)&xb;
    return (uint32_t)ra | ((uint32_t)rb << 16);
}
__device__ __forceinline__ uint32_t pkh(float a, float b) {     // fp16x2 pack
    __half2 h = __floats2half2_rn(a, b);
    return *(uint32_t*)&h;
}
__device__ __forceinline__ float bf_lo(uint32_t v) { return __uint_as_float(v << 16); }
__device__ __forceinline__ float bf_hi(uint32_t v) { return __uint_as_float(v & 0xffff0000u); }

__device__ __forceinline__ void mma16816(float* c, const uint32_t* a, const uint32_t* b) {
    asm volatile(
        "mma.sync.aligned.m16n8k16.row.col.f32.bf16.bf16.f32 "
        "{%0,%1,%2,%3}, {%4,%5,%6,%7}, {%8,%9}, {%0,%1,%2,%3};\n"
        : "+f"(c[0]), "+f"(c[1]), "+f"(c[2]), "+f"(c[3])
        : "r"(a[0]), "r"(a[1]), "r"(a[2]), "r"(a[3]), "r"(b[0]), "r"(b[1]));
}
__device__ __forceinline__ void mma16816h(float* c, const uint32_t* a, const uint32_t* b) {
    asm volatile(
        "mma.sync.aligned.m16n8k16.row.col.f32.f16.f16.f32 "
        "{%0,%1,%2,%3}, {%4,%5,%6,%7}, {%8,%9}, {%0,%1,%2,%3};\n"
        : "+f"(c[0]), "+f"(c[1]), "+f"(c[2]), "+f"(c[3])
        : "r"(a[0]), "r"(a[1]), "r"(a[2]), "r"(a[3]), "r"(b[0]), "r"(b[1]));
}
__device__ __forceinline__ void ldmx4(uint32_t* r, uint32_t addr) {
    asm volatile("ldmatrix.sync.aligned.m8n8.x4.shared.b16 {%0,%1,%2,%3}, [%4];"
        : "=r"(r[0]), "=r"(r[1]), "=r"(r[2]), "=r"(r[3]) : "r"(addr));
}
#define CP_ASYNC16(dst, src) asm volatile("cp.async.ca.shared.global [%0], [%1], 16;" :: "r"(dst), "l"(src))
#define CP_COMMIT()          asm volatile("cp.async.commit_group;" ::: "memory")
#define CP_WAIT(n)           asm volatile("cp.async.wait_group %0;" :: "n"(n) : "memory")

// ---------------- weight prep (3 launches so slot 4 = qkv GEMM in ncu) ----------------
__global__ void wprep_qkvw_kernel(const float* __restrict__ qkvw)
{
    int i = blockIdx.x * 256 + threadIdx.x;
    if (i < C3 * KDIM) {
        int n = i / KDIM, k = i % KDIM;
        float v = qkvw[(size_t)k * C3 + n];
        __half h = __float2half_rn(v);
        g_wqkv_h[i] = h;
        g_wqkv_l[i] = __float2half_rn(v - __half2float(h));
    }
}
__global__ void wprep_projw_kernel(const float* __restrict__ projw)
{
    int i = blockIdx.x * 256 + threadIdx.x;
    if (i < NC * KDIM) {
        int n = i / KDIM, k = i % KDIM;
        float v = projw[(size_t)k * NC + n];
        __half h = __float2half_rn(v);
        g_wproj_h[i] = h;
        g_wproj_l[i] = __float2half_rn(v - __half2float(h));
    }
}
__global__ void zero_kernel()
{
    int i = blockIdx.x * 256 + threadIdx.x;
    if (i < BNT * CH * CH) g_attn[i] = 0.f;
    if (i < BNT * CH) { g_ssq_q[i] = 0.f; g_ssq_k[i] = 0.f; }
}

// ---------------- fp16 2-term GEMM, warp tile 64x32 (4 mma/ldmatrix) ----------------
// D = A16*Bh + A16*Bl. CTA tile 128x64, 128 thr, 4 warps (2M x 2N), warp tile 64x32.
// smem 102400 -> 2 CTAs/SM.
#define ASTRIDE 200
#define ROWB    (ASTRIDE * 2)          // 400 bytes per row
#define OFF_A   0                       // 128 * 400 = 51200
#define OFF_BH  (128 * ROWB)            // 51200
#define OFF_BL  (128 * ROWB + 64 * ROWB)// 76800
#define GEMM_SMEM (128 * ROWB + 2 * 64 * ROWB)   // 102400

template<bool AHALF, bool OUTHALF>
__global__ __launch_bounds__(128, 2) void gemm_fp16_split(
    const void* __restrict__ Aptr, const __half* __restrict__ Wh,
    const __half* __restrict__ Wl, void* __restrict__ Coutp, int Ntot)
{
    extern __shared__ char smem[];
    const uint32_t sbase = smem_u32(smem);
    const uint32_t sA  = sbase + OFF_A;
    const uint32_t sBh = sbase + OFF_BH;
    const uint32_t sBl = sbase + OFF_BL;

    const int t = threadIdx.x;
    const int warp = t >> 5, lane = t & 31;
    const int grp = lane >> 2, tig = lane & 3;
    const int warpM = warp & 1, warpN = warp >> 1;      // 2 x 2, warp tile 64x32
    const size_t m0 = (size_t)blockIdx.x * 128;
    const int nChunks = Ntot >> 6;

    const uint32_t aOff = (uint32_t)(warpM * 64 + (lane & 15)) * ROWB + ((lane >> 4) * 16);
    const uint32_t bOff = (uint32_t)(warpN * 32 + ((lane >> 4) * 8) + (lane & 7)) * ROWB
                          + (((lane >> 3) & 1) * 16);

    // ---- issue B chunk 0 load ----
    {
        const uint4* bh = (const uint4*)Wh;
        const uint4* bl = (const uint4*)Wl;
#pragma unroll
        for (int i = t; i < 1536; i += 128) {          // 64 rows * 24 uint4
            int row = i / 24, cb = (i % 24) * 16;
            uint32_t o = (uint32_t)row * ROWB + cb;
            CP_ASYNC16(sBh + o, bh + i);
            CP_ASYNC16(sBl + o, bl + i);
        }
        CP_COMMIT();
    }
    // ---- A tile ----
    if (AHALF) {
        // fp16 rows: pure async copy, 128 rows * 24 uint4 = 3072
        const __half* Ah = (const __half*)Aptr;
#pragma unroll
        for (int i = t; i < 3072; i += 128) {
            int row = i / 24, seg = i % 24;
            const uint4* src = (const uint4*)(Ah + (m0 + row) * KDIM) + seg;
            CP_ASYNC16(sA + (uint32_t)row * ROWB + seg * 16, src);
        }
        CP_COMMIT();
    } else {
        const float* Af = (const float*)Aptr;
        int row = t;                        // one full row per thread
        const float4* ar = (const float4*)(Af + (m0 + row) * KDIM);
        __half* ap = (__half*)(smem + OFF_A) + row * ASTRIDE;
#pragma unroll
        for (int j = 0; j < 48; j++) {
            float4 v = ar[j];
            *(uint32_t*)(ap + j * 4)     = pkh(v.x, v.y);
            *(uint32_t*)(ap + j * 4 + 2) = pkh(v.z, v.w);
        }
    }
    CP_WAIT(0);
    __syncthreads();

    float c[4][4][4];   // mi (4 x 16-row frags) x nj (4 x 8-col frags)

    for (int nc = 0; nc < nChunks; nc++) {
#pragma unroll
        for (int mi = 0; mi < 4; mi++)
#pragma unroll
            for (int nj = 0; nj < 4; nj++)
#pragma unroll
                for (int j = 0; j < 4; j++) c[mi][nj][j] = 0.f;

#pragma unroll
        for (int ks = 0; ks < 12; ks++) {
            const uint32_t k32 = ks * 32;
            uint32_t a[4][4], bh0[4], bh1[4], bl0[4], bl1[4];
#pragma unroll
            for (int mi = 0; mi < 4; mi++)
                ldmx4(a[mi], sA + aOff + (uint32_t)(mi * 16) * ROWB + k32);
            ldmx4(bh0, sBh + bOff + k32);
            ldmx4(bh1, sBh + bOff + 16 * ROWB + k32);
            ldmx4(bl0, sBl + bOff + k32);
            ldmx4(bl1, sBl + bOff + 16 * ROWB + k32);
            // sweep 1: A * Bh (16 MMA, accumulator reuse distance 16)
#pragma unroll
            for (int mi = 0; mi < 4; mi++) {
                mma16816h(c[mi][0], a[mi], &bh0[0]);
                mma16816h(c[mi][1], a[mi], &bh0[2]);
                mma16816h(c[mi][2], a[mi], &bh1[0]);
                mma16816h(c[mi][3], a[mi], &bh1[2]);
            }
            // sweep 2: A * Bl (16 MMA)
#pragma unroll
            for (int mi = 0; mi < 4; mi++) {
                mma16816h(c[mi][0], a[mi], &bl0[0]);
                mma16816h(c[mi][1], a[mi], &bl0[2]);
                mma16816h(c[mi][2], a[mi], &bl1[0]);
                mma16816h(c[mi][3], a[mi], &bl1[2]);
            }
        }
        __syncthreads();   // all warps done reading this B chunk

        // issue next B chunk load (overlaps epilogue stores; partner CTA hides rest)
        if (nc + 1 < nChunks) {
            const uint4* bh = (const uint4*)(Wh + (size_t)(nc + 1) * 64 * KDIM);
            const uint4* bl = (const uint4*)(Wl + (size_t)(nc + 1) * 64 * KDIM);
#pragma unroll
            for (int i = t; i < 1536; i += 128) {
                int row = i / 24, cb = (i % 24) * 16;
                uint32_t o = (uint32_t)row * ROWB + cb;
                CP_ASYNC16(sBh + o, bh + i);
                CP_ASYNC16(sBl + o, bl + i);
            }
            CP_COMMIT();
        }

        // epilogue: store 128x64 chunk
        const int n0 = nc * 64;
#pragma unroll
        for (int mi = 0; mi < 4; mi++) {
            size_t row = m0 + warpM * 64 + mi * 16 + grp;
#pragma unroll
            for (int nj = 0; nj < 4; nj++) {
                int col = n0 + warpN * 32 + nj * 8 + tig * 2;
                if (OUTHALF) {
                    __half* co = (__half*)Coutp;
                    *(uint32_t*)(co + row * Ntot + col)       = pkh(c[mi][nj][0], c[mi][nj][1]);
                    *(uint32_t*)(co + (row + 8) * Ntot + col) = pkh(c[mi][nj][2], c[mi][nj][3]);
                } else {
                    float* co = (float*)Coutp;
                    *(float2*)(co + row * Ntot + col) = make_float2(c[mi][nj][0], c[mi][nj][1]);
                    *(float2*)(co + (row + 8) * Ntot + col) = make_float2(c[mi][nj][2], c[mi][nj][3]);
                }
            }
        }
        CP_WAIT(0);
        __syncthreads();
    }
}

// ---------------- depthwise 3x3 SAME + split (fp16 input; q/k -> bf16 hi/lo, v -> fp16) ----------------
__global__ __launch_bounds__(256) void dwconv_split_kernel(const float* __restrict__ w)
{
    int gid = blockIdx.x * 256 + threadIdx.x;
    int c4 = gid % 144;
    int p = gid / 144;
    int x = p % WW;
    int y = (p / WW) % HH;
    int b = p / HW;
    int c = c4 * 4;

    float4 acc = make_float4(0.f, 0.f, 0.f, 0.f);
#pragma unroll
    for (int dy = -1; dy <= 1; dy++) {
        int yy = y + dy;
        if (yy < 0 || yy >= HH) continue;
#pragma unroll
        for (int dx = -1; dx <= 1; dx++) {
            int xx = x + dx;
            if (xx < 0 || xx >= WW) continue;
            const __half2* iv2 = (const __half2*)(g_qkv_h + ((size_t)((b * HH + yy) * WW + xx)) * C3 + c);
            float2 p0 = __half22float2(iv2[0]);
            float2 p1 = __half22float2(iv2[1]);
            const float4 wv = *(const float4*)(w + (size_t)((dy + 1) * 3 + (dx + 1)) * C3 + c);
            acc.x = fmaf(p0.x, wv.x, acc.x);
            acc.y = fmaf(p0.y, wv.y, acc.y);
            acc.z = fmaf(p1.x, wv.z, acc.z);
            acc.w = fmaf(p1.y, wv.w, acc.w);
        }
    }
    if (c < NC) {
        int cc = c;
        *(uint2*)&g_qh[(size_t)p * NC + cc] = make_uint2(pk_hi(acc.x, acc.y), pk_hi(acc.z, acc.w));
        *(uint2*)&g_ql[(size_t)p * NC + cc] = make_uint2(pk_lo(acc.x, acc.y), pk_lo(acc.z, acc.w));
    } else if (c < 2 * NC) {
        int cc = c - NC;
        *(uint2*)&g_kh[(size_t)p * NC + cc] = make_uint2(pk_hi(acc.x, acc.y), pk_hi(acc.z, acc.w));
        *(uint2*)&g_kl[(size_t)p * NC + cc] = make_uint2(pk_lo(acc.x, acc.y), pk_lo(acc.z, acc.w));
    } else {
        int cc = c - 2 * NC;
        *(uint2*)&g_v_h[(size_t)p * NC + cc] = make_uint2(pkh(acc.x, acc.y), pkh(acc.z, acc.w));
    }
}

// ---------------- QK^T via mma.sync bf16-split + fused ssq ----------------
#define QK_PLANE 25344                     // 48 rows * 528 bytes
#define QK_SMEM  (4 * QK_PLANE)            // 101376

__global__ __launch_bounds__(256) void qk_mma_kernel()
{
    extern __shared__ char qsm[];
    const uint32_t sb = smem_u32(qsm);
    const int t = threadIdx.x, lane = t & 31, warp = t >> 5;
    const int grp = lane >> 2, tig = lane & 3;
    const int bn = blockIdx.x;
    const int sbase0 = blockIdx.y * 2048;

    const uint32_t aAddr = sb + (uint32_t)(lane & 15) * 528 + warp * 64 + ((lane >> 4) * 16);
    const uint32_t bAddr = sb + (uint32_t)(((lane >> 4) * 8) + (lane & 7)) * 528 + warp * 64
                           + (((lane >> 3) & 1) * 16);

    float c[3][6][4];
#pragma unroll
    for (int mi = 0; mi < 3; mi++)
#pragma unroll
        for (int nj = 0; nj < 6; nj++)
#pragma unroll
            for (int j = 0; j < 4; j++) c[mi][nj][j] = 0.f;
    float sq[3][2] = {{0.f,0.f},{0.f,0.f},{0.f,0.f}};
    float sk[3][2] = {{0.f,0.f},{0.f,0.f},{0.f,0.f}};

    for (int stage = 0; stage < 8; stage++) {
        const int sbase = sbase0 + stage * 256;
        const __nv_bfloat16* gp0 = g_qh; const __nv_bfloat16* gp1 = g_ql;
        const __nv_bfloat16* gp2 = g_kh; const __nv_bfloat16* gp3 = g_kl;
#pragma unroll
        for (int pl = 0; pl < 4; pl++) {
            const __nv_bfloat16* gp = (pl == 0) ? gp0 : (pl == 1) ? gp1 : (pl == 2) ? gp2 : gp3;
            uint32_t sp = sb + pl * QK_PLANE;
            for (int i = t; i < 1536; i += 256) {
                int r = i >> 5, seg = i & 31;
                const void* src = gp + (((size_t)(bn * 48 + r)) << 14) + sbase + seg * 8;
                CP_ASYNC16(sp + (uint32_t)r * 528 + seg * 16, src);
            }
        }
        CP_COMMIT();
        CP_WAIT(0);
        __syncthreads();

#pragma unroll
        for (int ks = 0; ks < 2; ks++) {
            const uint32_t kb = ks * 32;
            uint32_t ah[3][4], al[3][4], bh[3][4], bl[3][4];
#pragma unroll
            for (int mi = 0; mi < 3; mi++) {
                ldmx4(ah[mi], aAddr + (uint32_t)(mi * 16) * 528 + kb);
                ldmx4(al[mi], aAddr + QK_PLANE + (uint32_t)(mi * 16) * 528 + kb);
            }
#pragma unroll
            for (int pj = 0; pj < 3; pj++) {
                ldmx4(bh[pj], bAddr + 2 * QK_PLANE + (uint32_t)(pj * 16) * 528 + kb);
                ldmx4(bl[pj], bAddr + 3 * QK_PLANE + (uint32_t)(pj * 16) * 528 + kb);
            }
#pragma unroll
            for (int mi = 0; mi < 3; mi++)
#pragma unroll
                for (int r = 0; r < 4; r++) {
                    float f0 = bf_lo(ah[mi][r]) + bf_lo(al[mi][r]);
                    float f1 = bf_hi(ah[mi][r]) + bf_hi(al[mi][r]);
                    sq[mi][r & 1] = fmaf(f0, f0, fmaf(f1, f1, sq[mi][r & 1]));
                }
#pragma unroll
            for (int pj = 0; pj < 3; pj++)
#pragma unroll
                for (int r = 0; r < 4; r++) {
                    float f0 = bf_lo(bh[pj][r]) + bf_lo(bl[pj][r]);
                    float f1 = bf_hi(bh[pj][r]) + bf_hi(bl[pj][r]);
                    sk[pj][r >> 1] = fmaf(f0, f0, fmaf(f1, f1, sk[pj][r >> 1]));
                }
#pragma unroll
            for (int mi = 0; mi < 3; mi++)
#pragma unroll
                for (int pj = 0; pj < 3; pj++) {
                    mma16816(c[mi][2 * pj],     ah[mi], &bh[pj][0]);
                    mma16816(c[mi][2 * pj + 1], ah[mi], &bh[pj][2]);
                }
#pragma unroll
            for (int mi = 0; mi < 3; mi++)
#pragma unroll
                for (int pj = 0; pj < 3; pj++) {
                    mma16816(c[mi][2 * pj],     ah[mi], &bl[pj][0]);
                    mma16816(c[mi][2 * pj + 1], ah[mi], &bl[pj][2]);
                }
#pragma unroll
            for (int mi = 0; mi < 3; mi++)
#pragma unroll
                for (int pj = 0; pj < 3; pj++) {
                    mma16816(c[mi][2 * pj],     al[mi], &bh[pj][0]);
                    mma16816(c[mi][2 * pj + 1], al[mi], &bh[pj][2]);
                }
        }
        __syncthreads();
    }

    float* attn_s = (float*)qsm;
    float* ssq_qs = attn_s + 2304;
    float* ssq_ks = ssq_qs + 48;
    for (int i = t; i < 2400; i += 256) attn_s[i] = 0.f;
    __syncthreads();

#pragma unroll
    for (int mi = 0; mi < 3; mi++)
#pragma unroll
        for (int nj = 0; nj < 6; nj++) {
            int row = mi * 16 + grp, col = nj * 8 + tig * 2;
            atomicAdd(&attn_s[row * 48 + col],           c[mi][nj][0]);
            atomicAdd(&attn_s[row * 48 + col + 1],       c[mi][nj][1]);
            atomicAdd(&attn_s[(row + 8) * 48 + col],     c[mi][nj][2]);
            atomicAdd(&attn_s[(row + 8) * 48 + col + 1], c[mi][nj][3]);
        }
#pragma unroll
    for (int mi = 0; mi < 3; mi++)
#pragma unroll
        for (int h = 0; h < 2; h++) {
            float v = sq[mi][h];
            v += __shfl_xor_sync(~0u, v, 1);
            v += __shfl_xor_sync(~0u, v, 2);
            if (tig == 0) atomicAdd(&ssq_qs[mi * 16 + h * 8 + grp], v);
            float u = sk[mi][h];
            u += __shfl_xor_sync(~0u, u, 1);
            u += __shfl_xor_sync(~0u, u, 2);
            if (tig == 0) atomicAdd(&ssq_ks[mi * 16 + h * 8 + grp], u);
        }
    __syncthreads();

    for (int i = t; i < 2304; i += 256) atomicAdd(&g_attn[bn * 2304 + i], attn_s[i]);
    if (t < 48) atomicAdd(&g_ssq_q[bn * 48 + t], ssq_qs[t]);
    else if (t < 96) atomicAdd(&g_ssq_k[bn * 48 + t - 48], ssq_ks[t - 48]);
}

// ---------------- softmax with l2-norm scaling + temperature ----------------
__global__ void softmax48_kernel(const float* __restrict__ temp)
{
    int row = blockIdx.x;
    int bn = row / CH;
    int n = bn & (HEADS - 1);
    int l = threadIdx.x;
    float tf = temp[n];
    float iq = rsqrtf(fmaxf(g_ssq_q[row], 1e-12f));
    float* arow = g_attn + (size_t)row * CH;

    float ik0 = rsqrtf(fmaxf(g_ssq_k[bn * CH + l], 1e-12f));
    float v0 = arow[l] * iq * ik0 * tf;
    float v1 = -3.0e38f;
    if (l < 16) {
        float ik1 = rsqrtf(fmaxf(g_ssq_k[bn * CH + l + 32], 1e-12f));
        v1 = arow[l + 32] * iq * ik1 * tf;
    }
    float m = fmaxf(v0, v1);
#pragma unroll
    for (int o = 16; o > 0; o >>= 1) m = fmaxf(m, __shfl_xor_sync(~0u, m, o));
    float e0 = expf(v0 - m);
    float e1 = (l < 16) ? expf(v1 - m) : 0.f;
    float s = e0 + e1;
#pragma unroll
    for (int o = 16; o > 0; o >>= 1) s += __shfl_xor_sync(~0u, s, o);
    float inv = 1.f / s;
    arow[l] = e0 * inv;
    if (l < 16) arow[l + 32] = e1 * inv;
}

// ---------------- out = attn @ V (fp16 V in, fp16 O out) ----------------
__global__ __launch_bounds__(256) void av_kernel()
{
    int bn = blockIdx.x;
    int s2 = blockIdx.y * 256 + threadIdx.x;

    __shared__ float As[CH * CH];
    for (int f = threadIdx.x; f < CH * CH; f += 256) As[f] = g_attn[bn * CH * CH + f];
    __syncthreads();

    const __half2* vb = (const __half2*)(g_v_h + (size_t)bn * CH * HW) + s2;
    float2 vr[CH];
#pragma unroll
    for (int e = 0; e < CH; e++) vr[e] = __half22float2(vb[(size_t)e * (HW / 2)]);

    __half2* ob = (__half2*)(g_o_h + (size_t)bn * CH * HW) + s2;
    for (int d = 0; d < CH; d++) {
        float2 a = make_float2(0.f, 0.f);
#pragma unroll
        for (int e = 0; e < CH; e++) {
            float w = As[d * CH + e];
            a.x = fmaf(w, vr[e].x, a.x);
            a.y = fmaf(w, vr[e].y, a.y);
        }
        ob[(size_t)d * (HW / 2)] = __floats2half2_rn(a.x, a.y);
    }
}

// ---------------- launch ----------------
extern "C" void kernel_launch(void* const* d_in, const int* in_sizes, int n_in,
                              void* d_out, int out_size)
{
    const float* x      = (const float*)d_in[0];
    const float* qkv_w  = (const float*)d_in[1];
    const float* dw_w   = (const float*)d_in[2];
    const float* proj_w = (const float*)d_in[3];
    const float* temp   = (const float*)d_in[4];
    float* out = (float*)d_out;

    __half *qkv_buf, *o_buf;
    cudaGetSymbolAddress((void**)&qkv_buf, g_qkv_h);
    cudaGetSymbolAddress((void**)&o_buf, g_o_h);
    __half *wqh, *wql, *wph, *wpl;
    cudaGetSymbolAddress((void**)&wqh, g_wqkv_h);
    cudaGetSymbolAddress((void**)&wql, g_wqkv_l);
    cudaGetSymbolAddress((void**)&wph, g_wproj_h);
    cudaGetSymbolAddress((void**)&wpl, g_wproj_l);

    cudaFuncSetAttribute(gemm_fp16_split<false, true>, cudaFuncAttributeMaxDynamicSharedMemorySize, GEMM_SMEM);
    cudaFuncSetAttribute(gemm_fp16_split<true, false>, cudaFuncAttributeMaxDynamicSharedMemorySize, GEMM_SMEM);
    cudaFuncSetAttribute(qk_mma_kernel, cudaFuncAttributeMaxDynamicSharedMemorySize, QK_SMEM);

    const int M = NB * HW;

    // launches 1-3: prep (slot 4 = qkv GEMM gets profiled)
    wprep_qkvw_kernel<<<(C3 * KDIM + 255) / 256, 256>>>(qkv_w);
    wprep_projw_kernel<<<(NC * KDIM + 255) / 256, 256>>>(proj_w);
    zero_kernel<<<(BNT * CH * CH + 255) / 256, 256>>>();

    // 4) qkv = x @ qkv_w  (fp32 in, fp16 out)   <-- profiled slot
    gemm_fp16_split<false, true><<<M / 128, 128, GEMM_SMEM>>>(x, wqh, wql, qkv_buf, C3);

    // 5) depthwise 3x3 + split (fp16 in; q/k bf16 hi/lo, v fp16)
    dwconv_split_kernel<<<(NB * HW * (C3 / 4)) / 256, 256>>>(dw_w);

    // 6) QK^T (tensor cores) + fused square sums
    qk_mma_kernel<<<dim3(BNT, 8), 256, QK_SMEM>>>();

    // 7) scale + softmax
    softmax48_kernel<<<BNT * CH, 32>>>(temp);

    // 8) out = attn @ V (fp16 -> fp16)
    av_kernel<<<dim3(BNT, HW / 512), 256>>>();

    // 9) projection (fp16 in, fp32 out)
    gemm_fp16_split<true, false><<<M / 128, 128, GEMM_SMEM>>>(o_buf, wph, wpl, out, NC);
}

// round 15
// speedup vs baseline: 1.3110x; 1.2110x over previous
#include <cuda_runtime.h>
#include <cuda_bf16.h>
#include <cuda_fp16.h>
#include <math.h>
#include <stdint.h>

#define NB 8
#define HH 128
#define WW 128
#define NC 192
#define C3 576
#define HEADS 4
#define CH 48
#define HW 16384
#define BNT 32
#define KDIM 192

// ---------------- scratch ----------------
__device__ __half g_qkv_h[(size_t)NB * HW * C3];      // qkv intermediate, fp16
__device__ __nv_bfloat16 g_qh[(size_t)NB * HW * NC];
__device__ __nv_bfloat16 g_ql[(size_t)NB * HW * NC];
__device__ __nv_bfloat16 g_kh[(size_t)NB * HW * NC];
__device__ __nv_bfloat16 g_kl[(size_t)NB * HW * NC];
__device__ __half g_v_h[(size_t)NB * HW * NC];        // v, fp16
__device__ __half g_o_h[(size_t)NB * HW * NC];        // attn@V output, fp16
__device__ float g_attn[BNT * CH * CH];
__device__ float g_ssq_q[BNT * CH];
__device__ float g_ssq_k[BNT * CH];
// GEMM weights: fp16 (single plane), [N][K]
__device__ __half g_wqkv[C3 * KDIM];
__device__ __half g_wproj[NC * KDIM];

// ---------------- helpers ----------------
__device__ __forceinline__ uint32_t smem_u32(const void* p) {
    uint32_t a;
    asm("{ .reg .u64 t; cvta.to.shared.u64 t, %1; cvt.u32.u64 %0, t; }" : "=r"(a) : "l"(p));
    return a;
}
__device__ __forceinline__ uint32_t pk_hi(float a, float b) {   // bf16 pack (q/k path)
    __nv_bfloat16 ha = __float2bfloat16(a), hb = __float2bfloat16(b);
    uint16_t ra = *(uint16_t*)&ha, rb = *(uint16_t*)&hb;
    return (uint32_t)ra | ((uint32_t)rb << 16);
}
__device__ __forceinline__ uint32_t pk_lo(float a, float b) {
    __nv_bfloat16 ha = __float2bfloat16(a), hb = __float2bfloat16(b);
    float la = a - __bfloat162float(ha), lb = b - __bfloat162float(hb);
    __nv_bfloat16 xa = __float2bfloat16(la), xb = __float2bfloat16(lb);
    uint16_t ra = *(uint16_t*)&xa, rb = *(uint16_t*)&xb;
    return (uint32_t)ra | ((uint32_t)rb << 16);
}
__device__ __forceinline__ uint32_t pkh(float a, float b) {     // fp16x2 pack
    __half2 h = __floats2half2_rn(a, b);
    return *(uint32_t*)&h;
}
__device__ __forceinline__ float bf_lo(uint32_t v) { return __uint_as_float(v << 16); }
__device__ __forceinline__ float bf_hi(uint32_t v) { return __uint_as_float(v & 0xffff0000u); }

__device__ __forceinline__ void mma16816(float* c, const uint32_t* a, const uint32_t* b) {
    asm volatile(
        "mma.sync.aligned.m16n8k16.row.col.f32.bf16.bf16.f32 "
        "{%0,%1,%2,%3}, {%4,%5,%6,%7}, {%8,%9}, {%0,%1,%2,%3};\n"
        : "+f"(c[0]), "+f"(c[1]), "+f"(c[2]), "+f"(c[3])
        : "r"(a[0]), "r"(a[1]), "r"(a[2]), "r"(a[3]), "r"(b[0]), "r"(b[1]));
}
__device__ __forceinline__ void mma16816h(float* c, const uint32_t* a, const uint32_t* b) {
    asm volatile(
        "mma.sync.aligned.m16n8k16.row.col.f32.f16.f16.f32 "
        "{%0,%1,%2,%3}, {%4,%5,%6,%7}, {%8,%9}, {%0,%1,%2,%3};\n"
        : "+f"(c[0]), "+f"(c[1]), "+f"(c[2]), "+f"(c[3])
        : "r"(a[0]), "r"(a[1]), "r"(a[2]), "r"(a[3]), "r"(b[0]), "r"(b[1]));
}
__device__ __forceinline__ void ldmx4(uint32_t* r, uint32_t addr) {
    asm volatile("ldmatrix.sync.aligned.m8n8.x4.shared.b16 {%0,%1,%2,%3}, [%4];"
        : "=r"(r[0]), "=r"(r[1]), "=r"(r[2]), "=r"(r[3]) : "r"(addr));
}
#define CP_ASYNC16(dst, src) asm volatile("cp.async.ca.shared.global [%0], [%1], 16;" :: "r"(dst), "l"(src))
#define CP_COMMIT()          asm volatile("cp.async.commit_group;" ::: "memory")
#define CP_WAIT(n)           asm volatile("cp.async.wait_group %0;" :: "n"(n) : "memory")

// ---------------- weight prep (3 launches so slot 4 = qkv GEMM in ncu) ----------------
__global__ void wprep_qkvw_kernel(const float* __restrict__ qkvw)
{
    int i = blockIdx.x * 256 + threadIdx.x;
    if (i < C3 * KDIM) {
        int n = i / KDIM, k = i % KDIM;
        g_wqkv[i] = __float2half_rn(qkvw[(size_t)k * C3 + n]);
    }
}
__global__ void wprep_projw_kernel(const float* __restrict__ projw)
{
    int i = blockIdx.x * 256 + threadIdx.x;
    if (i < NC * KDIM) {
        int n = i / KDIM, k = i % KDIM;
        g_wproj[i] = __float2half_rn(projw[(size_t)k * NC + n]);
    }
}
__global__ void zero_kernel()
{
    int i = blockIdx.x * 256 + threadIdx.x;
    if (i < BNT * CH * CH) g_attn[i] = 0.f;
    if (i < BNT * CH) { g_ssq_q[i] = 0.f; g_ssq_k[i] = 0.f; }
}

// ---------------- fp16 single-pass GEMM, warp tile 64x32 ----------------
// D = A16 * B16. CTA tile 128x64, 128 thr, 4 warps (2M x 2N), warp tile 64x32.
// smem 76800 -> >=2 CTAs/SM (possibly 3).
#define ASTRIDE 200
#define ROWB    (ASTRIDE * 2)          // 400 bytes per row
#define OFF_A   0                       // 128 * 400 = 51200
#define OFF_B   (128 * ROWB)            // 51200
#define GEMM_SMEM (128 * ROWB + 64 * ROWB)   // 76800

template<bool AHALF, bool OUTHALF>
__global__ __launch_bounds__(128, 2) void gemm_fp16_1p(
    const void* __restrict__ Aptr, const __half* __restrict__ W,
    void* __restrict__ Coutp, int Ntot)
{
    extern __shared__ char smem[];
    const uint32_t sbase = smem_u32(smem);
    const uint32_t sA = sbase + OFF_A;
    const uint32_t sB = sbase + OFF_B;

    const int t = threadIdx.x;
    const int warp = t >> 5, lane = t & 31;
    const int grp = lane >> 2, tig = lane & 3;
    const int warpM = warp & 1, warpN = warp >> 1;      // 2 x 2, warp tile 64x32
    const size_t m0 = (size_t)blockIdx.x * 128;
    const int nChunks = Ntot >> 6;

    const uint32_t aOff = (uint32_t)(warpM * 64 + (lane & 15)) * ROWB + ((lane >> 4) * 16);
    const uint32_t bOff = (uint32_t)(warpN * 32 + ((lane >> 4) * 8) + (lane & 7)) * ROWB
                          + (((lane >> 3) & 1) * 16);

    // ---- issue B chunk 0 load ----
    {
        const uint4* bw = (const uint4*)W;
#pragma unroll
        for (int i = t; i < 1536; i += 128) {          // 64 rows * 24 uint4
            int row = i / 24, cb = (i % 24) * 16;
            CP_ASYNC16(sB + (uint32_t)row * ROWB + cb, bw + i);
        }
        CP_COMMIT();
    }
    // ---- A tile ----
    if (AHALF) {
        const __half* Ah = (const __half*)Aptr;
#pragma unroll
        for (int i = t; i < 3072; i += 128) {          // 128 rows * 24 uint4
            int row = i / 24, seg = i % 24;
            const uint4* src = (const uint4*)(Ah + (m0 + row) * KDIM) + seg;
            CP_ASYNC16(sA + (uint32_t)row * ROWB + seg * 16, src);
        }
        CP_COMMIT();
    } else {
        const float* Af = (const float*)Aptr;
        int row = t;                        // one full row per thread
        const float4* ar = (const float4*)(Af + (m0 + row) * KDIM);
        __half* ap = (__half*)(smem + OFF_A) + row * ASTRIDE;
#pragma unroll
        for (int j = 0; j < 48; j++) {
            float4 v = ar[j];
            *(uint32_t*)(ap + j * 4)     = pkh(v.x, v.y);
            *(uint32_t*)(ap + j * 4 + 2) = pkh(v.z, v.w);
        }
    }
    CP_WAIT(0);
    __syncthreads();

    float c[4][4][4];   // mi (4 x 16-row frags) x nj (4 x 8-col frags)

    for (int nc = 0; nc < nChunks; nc++) {
#pragma unroll
        for (int mi = 0; mi < 4; mi++)
#pragma unroll
            for (int nj = 0; nj < 4; nj++)
#pragma unroll
                for (int j = 0; j < 4; j++) c[mi][nj][j] = 0.f;

#pragma unroll
        for (int ks = 0; ks < 12; ks++) {
            const uint32_t k32 = ks * 32;
            uint32_t a[4][4], b0[4], b1[4];
#pragma unroll
            for (int mi = 0; mi < 4; mi++)
                ldmx4(a[mi], sA + aOff + (uint32_t)(mi * 16) * ROWB + k32);
            ldmx4(b0, sB + bOff + k32);
            ldmx4(b1, sB + bOff + 16 * ROWB + k32);
            // 16 MMA, accumulator reuse distance 16
#pragma unroll
            for (int mi = 0; mi < 4; mi++) {
                mma16816h(c[mi][0], a[mi], &b0[0]);
                mma16816h(c[mi][1], a[mi], &b0[2]);
                mma16816h(c[mi][2], a[mi], &b1[0]);
                mma16816h(c[mi][3], a[mi], &b1[2]);
            }
        }
        __syncthreads();   // all warps done reading this B chunk

        // issue next B chunk load (overlaps epilogue stores; partner CTA hides rest)
        if (nc + 1 < nChunks) {
            const uint4* bw = (const uint4*)(W + (size_t)(nc + 1) * 64 * KDIM);
#pragma unroll
            for (int i = t; i < 1536; i += 128) {
                int row = i / 24, cb = (i % 24) * 16;
                CP_ASYNC16(sB + (uint32_t)row * ROWB + cb, bw + i);
            }
            CP_COMMIT();
        }

        // epilogue: store 128x64 chunk
        const int n0 = nc * 64;
#pragma unroll
        for (int mi = 0; mi < 4; mi++) {
            size_t row = m0 + warpM * 64 + mi * 16 + grp;
#pragma unroll
            for (int nj = 0; nj < 4; nj++) {
                int col = n0 + warpN * 32 + nj * 8 + tig * 2;
                if (OUTHALF) {
                    __half* co = (__half*)Coutp;
                    *(uint32_t*)(co + row * Ntot + col)       = pkh(c[mi][nj][0], c[mi][nj][1]);
                    *(uint32_t*)(co + (row + 8) * Ntot + col) = pkh(c[mi][nj][2], c[mi][nj][3]);
                } else {
                    float* co = (float*)Coutp;
                    *(float2*)(co + row * Ntot + col) = make_float2(c[mi][nj][0], c[mi][nj][1]);
                    *(float2*)(co + (row + 8) * Ntot + col) = make_float2(c[mi][nj][2], c[mi][nj][3]);
                }
            }
        }
        CP_WAIT(0);
        __syncthreads();
    }
}

// ---------------- depthwise 3x3 SAME + split (fp16 input; q/k -> bf16 hi/lo, v -> fp16) ----------------
__global__ __launch_bounds__(256) void dwconv_split_kernel(const float* __restrict__ w)
{
    int gid = blockIdx.x * 256 + threadIdx.x;
    int c4 = gid % 144;
    int p = gid / 144;
    int x = p % WW;
    int y = (p / WW) % HH;
    int b = p / HW;
    int c = c4 * 4;

    float4 acc = make_float4(0.f, 0.f, 0.f, 0.f);
#pragma unroll
    for (int dy = -1; dy <= 1; dy++) {
        int yy = y + dy;
        if (yy < 0 || yy >= HH) continue;
#pragma unroll
        for (int dx = -1; dx <= 1; dx++) {
            int xx = x + dx;
            if (xx < 0 || xx >= WW) continue;
            const __half2* iv2 = (const __half2*)(g_qkv_h + ((size_t)((b * HH + yy) * WW + xx)) * C3 + c);
            float2 p0 = __half22float2(iv2[0]);
            float2 p1 = __half22float2(iv2[1]);
            const float4 wv = *(const float4*)(w + (size_t)((dy + 1) * 3 + (dx + 1)) * C3 + c);
            acc.x = fmaf(p0.x, wv.x, acc.x);
            acc.y = fmaf(p0.y, wv.y, acc.y);
            acc.z = fmaf(p1.x, wv.z, acc.z);
            acc.w = fmaf(p1.y, wv.w, acc.w);
        }
    }
    if (c < NC) {
        int cc = c;
        *(uint2*)&g_qh[(size_t)p * NC + cc] = make_uint2(pk_hi(acc.x, acc.y), pk_hi(acc.z, acc.w));
        *(uint2*)&g_ql[(size_t)p * NC + cc] = make_uint2(pk_lo(acc.x, acc.y), pk_lo(acc.z, acc.w));
    } else if (c < 2 * NC) {
        int cc = c - NC;
        *(uint2*)&g_kh[(size_t)p * NC + cc] = make_uint2(pk_hi(acc.x, acc.y), pk_hi(acc.z, acc.w));
        *(uint2*)&g_kl[(size_t)p * NC + cc] = make_uint2(pk_lo(acc.x, acc.y), pk_lo(acc.z, acc.w));
    } else {
        int cc = c - 2 * NC;
        *(uint2*)&g_v_h[(size_t)p * NC + cc] = make_uint2(pkh(acc.x, acc.y), pkh(acc.z, acc.w));
    }
}

// ---------------- QK^T via mma.sync bf16-split + fused ssq ----------------
#define QK_PLANE 25344                     // 48 rows * 528 bytes
#define QK_SMEM  (4 * QK_PLANE)            // 101376

__global__ __launch_bounds__(256) void qk_mma_kernel()
{
    extern __shared__ char qsm[];
    const uint32_t sb = smem_u32(qsm);
    const int t = threadIdx.x, lane = t & 31, warp = t >> 5;
    const int grp = lane >> 2, tig = lane & 3;
    const int bn = blockIdx.x;
    const int sbase0 = blockIdx.y * 2048;

    const uint32_t aAddr = sb + (uint32_t)(lane & 15) * 528 + warp * 64 + ((lane >> 4) * 16);
    const uint32_t bAddr = sb + (uint32_t)(((lane >> 4) * 8) + (lane & 7)) * 528 + warp * 64
                           + (((lane >> 3) & 1) * 16);

    float c[3][6][4];
#pragma unroll
    for (int mi = 0; mi < 3; mi++)
#pragma unroll
        for (int nj = 0; nj < 6; nj++)
#pragma unroll
            for (int j = 0; j < 4; j++) c[mi][nj][j] = 0.f;
    float sq[3][2] = {{0.f,0.f},{0.f,0.f},{0.f,0.f}};
    float sk[3][2] = {{0.f,0.f},{0.f,0.f},{0.f,0.f}};

    for (int stage = 0; stage < 8; stage++) {
        const int sbase = sbase0 + stage * 256;
        const __nv_bfloat16* gp0 = g_qh; const __nv_bfloat16* gp1 = g_ql;
        const __nv_bfloat16* gp2 = g_kh; const __nv_bfloat16* gp3 = g_kl;
#pragma unroll
        for (int pl = 0; pl < 4; pl++) {
            const __nv_bfloat16* gp = (pl == 0) ? gp0 : (pl == 1) ? gp1 : (pl == 2) ? gp2 : gp3;
            uint32_t sp = sb + pl * QK_PLANE;
            for (int i = t; i < 1536; i += 256) {
                int r = i >> 5, seg = i & 31;
                const void* src = gp + (((size_t)(bn * 48 + r)) << 14) + sbase + seg * 8;
                CP_ASYNC16(sp + (uint32_t)r * 528 + seg * 16, src);
            }
        }
        CP_COMMIT();
        CP_WAIT(0);
        __syncthreads();

#pragma unroll
        for (int ks = 0; ks < 2; ks++) {
            const uint32_t kb = ks * 32;
            uint32_t ah[3][4], al[3][4], bh[3][4], bl[3][4];
#pragma unroll
            for (int mi = 0; mi < 3; mi++) {
                ldmx4(ah[mi], aAddr + (uint32_t)(mi * 16) * 528 + kb);
                ldmx4(al[mi], aAddr + QK_PLANE + (uint32_t)(mi * 16) * 528 + kb);
            }
#pragma unroll
            for (int pj = 0; pj < 3; pj++) {
                ldmx4(bh[pj], bAddr + 2 * QK_PLANE + (uint32_t)(pj * 16) * 528 + kb);
                ldmx4(bl[pj], bAddr + 3 * QK_PLANE + (uint32_t)(pj * 16) * 528 + kb);
            }
#pragma unroll
            for (int mi = 0; mi < 3; mi++)
#pragma unroll
                for (int r = 0; r < 4; r++) {
                    float f0 = bf_lo(ah[mi][r]) + bf_lo(al[mi][r]);
                    float f1 = bf_hi(ah[mi][r]) + bf_hi(al[mi][r]);
                    sq[mi][r & 1] = fmaf(f0, f0, fmaf(f1, f1, sq[mi][r & 1]));
                }
#pragma unroll
            for (int pj = 0; pj < 3; pj++)
#pragma unroll
                for (int r = 0; r < 4; r++) {
                    float f0 = bf_lo(bh[pj][r]) + bf_lo(bl[pj][r]);
                    float f1 = bf_hi(bh[pj][r]) + bf_hi(bl[pj][r]);
                    sk[pj][r >> 1] = fmaf(f0, f0, fmaf(f1, f1, sk[pj][r >> 1]));
                }
#pragma unroll
            for (int mi = 0; mi < 3; mi++)
#pragma unroll
                for (int pj = 0; pj < 3; pj++) {
                    mma16816(c[mi][2 * pj],     ah[mi], &bh[pj][0]);
                    mma16816(c[mi][2 * pj + 1], ah[mi], &bh[pj][2]);
                }
#pragma unroll
            for (int mi = 0; mi < 3; mi++)
#pragma unroll
                for (int pj = 0; pj < 3; pj++) {
                    mma16816(c[mi][2 * pj],     ah[mi], &bl[pj][0]);
                    mma16816(c[mi][2 * pj + 1], ah[mi], &bl[pj][2]);
                }
#pragma unroll
            for (int mi = 0; mi < 3; mi++)
#pragma unroll
                for (int pj = 0; pj < 3; pj++) {
                    mma16816(c[mi][2 * pj],     al[mi], &bh[pj][0]);
                    mma16816(c[mi][2 * pj + 1], al[mi], &bh[pj][2]);
                }
        }
        __syncthreads();
    }

    float* attn_s = (float*)qsm;
    float* ssq_qs = attn_s + 2304;
    float* ssq_ks = ssq_qs + 48;
    for (int i = t; i < 2400; i += 256) attn_s[i] = 0.f;
    __syncthreads();

#pragma unroll
    for (int mi = 0; mi < 3; mi++)
#pragma unroll
        for (int nj = 0; nj < 6; nj++) {
            int row = mi * 16 + grp, col = nj * 8 + tig * 2;
            atomicAdd(&attn_s[row * 48 + col],           c[mi][nj][0]);
            atomicAdd(&attn_s[row * 48 + col + 1],       c[mi][nj][1]);
            atomicAdd(&attn_s[(row + 8) * 48 + col],     c[mi][nj][2]);
            atomicAdd(&attn_s[(row + 8) * 48 + col + 1], c[mi][nj][3]);
        }
#pragma unroll
    for (int mi = 0; mi < 3; mi++)
#pragma unroll
        for (int h = 0; h < 2; h++) {
            float v = sq[mi][h];
            v += __shfl_xor_sync(~0u, v, 1);
            v += __shfl_xor_sync(~0u, v, 2);
            if (tig == 0) atomicAdd(&ssq_qs[mi * 16 + h * 8 + grp], v);
            float u = sk[mi][h];
            u += __shfl_xor_sync(~0u, u, 1);
            u += __shfl_xor_sync(~0u, u, 2);
            if (tig == 0) atomicAdd(&ssq_ks[mi * 16 + h * 8 + grp], u);
        }
    __syncthreads();

    for (int i = t; i < 2304; i += 256) atomicAdd(&g_attn[bn * 2304 + i], attn_s[i]);
    if (t < 48) atomicAdd(&g_ssq_q[bn * 48 + t], ssq_qs[t]);
    else if (t < 96) atomicAdd(&g_ssq_k[bn * 48 + t - 48], ssq_ks[t - 48]);
}

// ---------------- softmax with l2-norm scaling + temperature ----------------
__global__ void softmax48_kernel(const float* __restrict__ temp)
{
    int row = blockIdx.x;
    int bn = row / CH;
    int n = bn & (HEADS - 1);
    int l = threadIdx.x;
    float tf = temp[n];
    float iq = rsqrtf(fmaxf(g_ssq_q[row], 1e-12f));
    float* arow = g_attn + (size_t)row * CH;

    float ik0 = rsqrtf(fmaxf(g_ssq_k[bn * CH + l], 1e-12f));
    float v0 = arow[l] * iq * ik0 * tf;
    float v1 = -3.0e38f;
    if (l < 16) {
        float ik1 = rsqrtf(fmaxf(g_ssq_k[bn * CH + l + 32], 1e-12f));
        v1 = arow[l + 32] * iq * ik1 * tf;
    }
    float m = fmaxf(v0, v1);
#pragma unroll
    for (int o = 16; o > 0; o >>= 1) m = fmaxf(m, __shfl_xor_sync(~0u, m, o));
    float e0 = expf(v0 - m);
    float e1 = (l < 16) ? expf(v1 - m) : 0.f;
    float s = e0 + e1;
#pragma unroll
    for (int o = 16; o > 0; o >>= 1) s += __shfl_xor_sync(~0u, s, o);
    float inv = 1.f / s;
    arow[l] = e0 * inv;
    if (l < 16) arow[l + 32] = e1 * inv;
}

// ---------------- out = attn @ V (fp16 V in, fp16 O out) ----------------
__global__ __launch_bounds__(256) void av_kernel()
{
    int bn = blockIdx.x;
    int s2 = blockIdx.y * 256 + threadIdx.x;

    __shared__ float As[CH * CH];
    for (int f = threadIdx.x; f < CH * CH; f += 256) As[f] = g_attn[bn * CH * CH + f];
    __syncthreads();

    const __half2* vb = (const __half2*)(g_v_h + (size_t)bn * CH * HW) + s2;
    float2 vr[CH];
#pragma unroll
    for (int e = 0; e < CH; e++) vr[e] = __half22float2(vb[(size_t)e * (HW / 2)]);

    __half2* ob = (__half2*)(g_o_h + (size_t)bn * CH * HW) + s2;
    for (int d = 0; d < CH; d++) {
        float2 a = make_float2(0.f, 0.f);
#pragma unroll
        for (int e = 0; e < CH; e++) {
            float w = As[d * CH + e];
            a.x = fmaf(w, vr[e].x, a.x);
            a.y = fmaf(w, vr[e].y, a.y);
        }
        ob[(size_t)d * (HW / 2)] = __floats2half2_rn(a.x, a.y);
    }
}

// ---------------- launch ----------------
extern "C" void kernel_launch(void* const* d_in, const int* in_sizes, int n_in,
                              void* d_out, int out_size)
{
    const float* x      = (const float*)d_in[0];
    const float* qkv_w  = (const float*)d_in[1];
    const float* dw_w   = (const float*)d_in[2];
    const float* proj_w = (const float*)d_in[3];
    const float* temp   = (const float*)d_in[4];
    float* out = (float*)d_out;

    __half *qkv_buf, *o_buf;
    cudaGetSymbolAddress((void**)&qkv_buf, g_qkv_h);
    cudaGetSymbolAddress((void**)&o_buf, g_o_h);
    __half *wq, *wp;
    cudaGetSymbolAddress((void**)&wq, g_wqkv);
    cudaGetSymbolAddress((void**)&wp, g_wproj);

    cudaFuncSetAttribute(gemm_fp16_1p<false, true>, cudaFuncAttributeMaxDynamicSharedMemorySize, GEMM_SMEM);
    cudaFuncSetAttribute(gemm_fp16_1p<true, false>, cudaFuncAttributeMaxDynamicSharedMemorySize, GEMM_SMEM);
    cudaFuncSetAttribute(qk_mma_kernel, cudaFuncAttributeMaxDynamicSharedMemorySize, QK_SMEM);

    const int M = NB * HW;

    // launches 1-3: prep (slot 4 = qkv GEMM gets profiled)
    wprep_qkvw_kernel<<<(C3 * KDIM + 255) / 256, 256>>>(qkv_w);
    wprep_projw_kernel<<<(NC * KDIM + 255) / 256, 256>>>(proj_w);
    zero_kernel<<<(BNT * CH * CH + 255) / 256, 256>>>();

    // 4) qkv = x @ qkv_w  (fp32 in, fp16 out)   <-- profiled slot
    gemm_fp16_1p<false, true><<<M / 128, 128, GEMM_SMEM>>>(x, wq, qkv_buf, C3);

    // 5) depthwise 3x3 + split (fp16 in; q/k bf16 hi/lo, v fp16)
    dwconv_split_kernel<<<(NB * HW * (C3 / 4)) / 256, 256>>>(dw_w);

    // 6) QK^T (tensor cores) + fused square sums
    qk_mma_kernel<<<dim3(BNT, 8), 256, QK_SMEM>>>();

    // 7) scale + softmax
    softmax48_kernel<<<BNT * CH, 32>>>(temp);

    // 8) out = attn @ V (fp16 -> fp16)
    av_kernel<<<dim3(BNT, HW / 512), 256>>>();

    // 9) projection (fp16 in, fp32 out)
    gemm_fp16_1p<true, false><<<M / 128, 128, GEMM_SMEM>>>(o_buf, wp, out, NC);
}